// round 3
// baseline (speedup 1.0000x reference)
#include <cuda_runtime.h>
#include <math.h>

#define HW      16384
#define KJ      300
#define NLINES  49152
#define NBMW    2816            // 2816*32 = 90112 >= 90000 bits
#define MPAD    44928           // ceil(44850/128)*128
#define PI_F    3.14159265358979323846f

// ---------------- scratch (static device memory; no allocations) ----------------
__device__ float               g_jloc[HW];
__device__ float               g_nms[HW];
__device__ unsigned long long  g_cand[4096];
__device__ int                 g_ccount;
__device__ float               g_junc[2 * KJ];
__device__ unsigned int        g_bitmap[NBMW];
__device__ int                 g_count;
__device__ float               g_fc1t[256 * 128];
__device__ float               g_loi[(size_t)HW * 128];      // [pixel][channel]
__device__ float               g_bufA[(size_t)MPAD * 1024];  // feats -> h2
__device__ float               g_bufB[(size_t)MPAD * 1024];  // h1

__device__ __forceinline__ float sigm(float x) { return 1.0f / (1.0f + expf(-x)); }

// ---------------- stage 1: jloc = softmax(ch5,ch6)[1] ----------------
__global__ void k_jloc(const float* __restrict__ heat) {
    int i = blockIdx.x * blockDim.x + threadIdx.x;
    if (i < HW) g_jloc[i] = 1.0f / (1.0f + expf(heat[5 * HW + i] - heat[6 * HW + i]));
}

// ---------------- stage 2: 3x3 NMS ----------------
__global__ void k_nms(void) {
    int i = blockIdx.x * blockDim.x + threadIdx.x;
    if (i >= HW) return;
    int y = i >> 7, x = i & 127;
    float m = -1e30f;
    for (int dy = -1; dy <= 1; dy++) {
        int yy = y + dy; if ((unsigned)yy >= 128u) continue;
        for (int dx = -1; dx <= 1; dx++) {
            int xx = x + dx; if ((unsigned)xx >= 128u) continue;
            m = fmaxf(m, g_jloc[yy * 128 + xx]);
        }
    }
    float v = g_jloc[i];
    g_nms[i] = (v == m) ? v : 0.0f;
}

// ---------------- stage 3: gather nonzero candidates ----------------
// 3x3 strict local maxima are non-adjacent -> at most 64*64 = 4096 of them.
__global__ void k_cand(void) {
    int i = blockIdx.x * blockDim.x + threadIdx.x;
    if (i >= HW) return;
    float v = g_nms[i];
    if (v > 0.0f) {
        int p = atomicAdd(&g_ccount, 1);
        if (p < 4096) {
            unsigned long long key =
                ((unsigned long long)__float_as_uint(v) << 32) |
                (unsigned long long)(0xFFFFFFFFu - (unsigned)i);   // ties: lower idx first
            g_cand[p] = key;
        }
    }
}

// ---------------- stage 4: bitonic sort (desc) + junction coords ----------------
__global__ void k_topk(const float* __restrict__ heat) {
    __shared__ unsigned long long s[4096];
    int tid = threadIdx.x;
    for (int q = 0; q < 4; q++) s[q * 1024 + tid] = g_cand[q * 1024 + tid];
    __syncthreads();
    for (int k = 2; k <= 4096; k <<= 1) {
        for (int j = k >> 1; j > 0; j >>= 1) {
            for (int q = 0; q < 4; q++) {
                int i = q * 1024 + tid;
                int ixj = i ^ j;
                if (ixj > i) {
                    unsigned long long a = s[i], b = s[ixj];
                    bool descSeg = (i & k) == 0;
                    bool sw = descSeg ? (a < b) : (a > b);
                    if (sw) { s[i] = b; s[ixj] = a; }
                }
            }
            __syncthreads();
        }
    }
    if (tid < KJ) {
        unsigned long long key = s[tid];
        float v = __uint_as_float((unsigned)(key >> 32));
        if (v > 0.008f) {
            unsigned pix = 0xFFFFFFFFu - (unsigned)(key & 0xFFFFFFFFu);
            float x = (float)(pix & 127u), y = (float)(pix >> 7);
            g_junc[2 * tid + 0] = x + sigm(heat[7 * HW + pix]);
            g_junc[2 * tid + 1] = y + sigm(heat[8 * HW + pix]);
        } else {
            g_junc[2 * tid + 0] = 1e6f;
            g_junc[2 * tid + 1] = 1e6f;
        }
    }
}

// ---------------- stage 5: HAFM decode + junction matching + id bitmap ----------------
__global__ void k_match(const float* __restrict__ heat) {
    __shared__ float sj[2 * KJ];
    for (int i = threadIdx.x; i < 2 * KJ; i += blockDim.x) sj[i] = g_junc[i];
    __syncthreads();
    int n = blockIdx.x * blockDim.x + threadIdx.x;
    if (n >= NLINES) return;
    int ch = n >> 14;
    int pix = n & (HW - 1);
    float x0 = (float)(pix & 127), y0 = (float)(pix >> 7);
    float a0   = sigm(heat[0 * HW + pix]);
    float a1   = sigm(heat[1 * HW + pix]);
    float a2   = sigm(heat[2 * HW + pix]);
    float dist = sigm(heat[3 * HW + pix]);
    float bias = sigm(heat[4 * HW + pix]);
    float d = dist + bias * (float)(ch - 1);
    d = fminf(fmaxf(d, 0.0f), 1.0f);
    float ang0 = (a0 - 0.5f) * PI_F * 2.0f;
    float c0 = cosf(ang0), s0 = sinf(ang0);
    float t1 =  tanf(a1 * (PI_F * 0.5f));
    float t2 = -tanf(a2 * (PI_F * 0.5f));
    float e1x = fminf(fmaxf((c0 - s0 * t1) * d * 5.0f + x0, 0.0f), 127.0f);
    float e1y = fminf(fmaxf((s0 + c0 * t1) * d * 5.0f + y0, 0.0f), 127.0f);
    float e2x = fminf(fmaxf((c0 - s0 * t2) * d * 5.0f + x0, 0.0f), 127.0f);
    float e2y = fminf(fmaxf((s0 + c0 * t2) * d * 5.0f + y0, 0.0f), 127.0f);

    int j1 = 0, j2 = 0;
    float m1 = 3.4e38f, m2 = 3.4e38f;
    #pragma unroll 4
    for (int k = 0; k < KJ; k++) {
        float jx = sj[2 * k], jy = sj[2 * k + 1];
        float dx = jx - e1x, dy = jy - e1y;
        float dd = dx * dx + dy * dy;
        if (dd < m1) { m1 = dd; j1 = k; }
        dx = jx - e2x; dy = jy - e2y;
        dd = dx * dx + dy * dy;
        if (dd < m2) { m2 = dd; j2 = k; }
    }
    int lo = min(j1, j2), hi = max(j1, j2);
    if (lo < hi) {
        int id = lo * KJ + hi;
        atomicOr(&g_bitmap[id >> 5], 1u << (id & 31));
    }
}

// ---------------- stage 6: ordered bitmap compaction -> sorted unique ids ----------------
__global__ void k_compact(float* __restrict__ dout) {
    __shared__ int sc[1024];
    int tid = threadIdx.x;
    int base = tid * 3;
    unsigned w[3] = {0u, 0u, 0u};
    int c = 0;
    #pragma unroll
    for (int q = 0; q < 3; q++) {
        int wi = base + q;
        if (wi < NBMW) { w[q] = g_bitmap[wi]; c += __popc(w[q]); }
    }
    sc[tid] = c;
    __syncthreads();
    for (int off = 1; off < 1024; off <<= 1) {
        int v = 0;
        if (tid >= off) v = sc[tid - off];
        __syncthreads();
        if (tid >= off) sc[tid] += v;
        __syncthreads();
    }
    int pos = sc[tid] - c;     // exclusive prefix
    #pragma unroll
    for (int q = 0; q < 3; q++) {
        unsigned ww = w[q];
        int wbase = (base + q) * 32;
        while (ww) {
            int b = __ffs(ww) - 1;
            ww &= ww - 1;
            int id = wbase + b;
            int lo = id / KJ, hi = id - lo * KJ;
            dout[pos * 4 + 0] = g_junc[2 * lo + 0];
            dout[pos * 4 + 1] = g_junc[2 * lo + 1];
            dout[pos * 4 + 2] = g_junc[2 * hi + 0];
            dout[pos * 4 + 3] = g_junc[2 * hi + 1];
            pos++;
        }
    }
    if (tid == 1023) g_count = sc[1023];
}

// ---------------- stage 7a: transpose fc1_w -> [c][o] ----------------
__global__ void k_tr(const float* __restrict__ fc1w) {
    int i = blockIdx.x * blockDim.x + threadIdx.x;   // i = c*128 + o
    if (i < 256 * 128) {
        int cc = i >> 7, o = i & 127;
        g_fc1t[i] = fc1w[o * 256 + cc];
    }
}

// ---------------- stage 7b: LOI GEMM  loi[p][o] = sum_c feat[c][p]*w[o][c] + b[o] ----------------
__global__ void k_loi(const float* __restrict__ feat, const float* __restrict__ fc1b) {
    __shared__ float As[8][128];   // [kc][p]
    __shared__ float Bs[8][128];   // [kc][o]
    float acc[8][8];
    #pragma unroll
    for (int r = 0; r < 8; r++)
        #pragma unroll
        for (int j = 0; j < 8; j++) acc[r][j] = 0.0f;
    int tid = threadIdx.x;
    int tx = tid & 15, ty = tid >> 4;
    int p0 = blockIdx.x * 128;
    for (int c0 = 0; c0 < 256; c0 += 8) {
        #pragma unroll
        for (int q = 0; q < 4; q++) {
            int idx = tid + q * 256;
            int kc = idx >> 7, col = idx & 127;
            As[kc][col] = feat[(size_t)(c0 + kc) * HW + p0 + col];
            Bs[kc][col] = g_fc1t[(c0 + kc) * 128 + col];
        }
        __syncthreads();
        #pragma unroll
        for (int kc = 0; kc < 8; kc++) {
            float a[8], b[8];
            #pragma unroll
            for (int r = 0; r < 8; r++) a[r] = As[kc][ty + 16 * r];
            #pragma unroll
            for (int j = 0; j < 8; j++) b[j] = Bs[kc][tx + 16 * j];
            #pragma unroll
            for (int r = 0; r < 8; r++)
                #pragma unroll
                for (int j = 0; j < 8; j++) acc[r][j] += a[r] * b[j];
        }
        __syncthreads();
    }
    #pragma unroll
    for (int r = 0; r < 8; r++) {
        int p = p0 + ty + 16 * r;
        #pragma unroll
        for (int j = 0; j < 8; j++) {
            int o = tx + 16 * j;
            g_loi[(size_t)p * 128 + o] = acc[r][j] + fc1b[o];
        }
    }
}

// ---------------- stage 8: bilinear sampling + maxpool4 -> feats[m][1024] ----------------
__global__ void k_sample(const float* __restrict__ dout) {
    int M = g_count;
    int ch = threadIdx.x;      // 128 threads, one channel each
    for (int m = blockIdx.x; m < M; m += gridDim.x) {
        float x1 = dout[m * 4 + 0], y1 = dout[m * 4 + 1];
        float x2 = dout[m * 4 + 2], y2 = dout[m * 4 + 3];
        float mx = -3.4e38f;
        #pragma unroll 4
        for (int s = 0; s < 32; s++) {
            float t = (float)s / 31.0f;
            float px = x1 * t + x2 * (1.0f - t);
            float py = y1 * t + y2 * (1.0f - t);
            px = fminf(fmaxf(px, 0.0f), 127.0f);
            py = fminf(fmaxf(py, 0.0f), 127.0f);
            float fx0 = floorf(px), fy0 = floorf(py);
            int ix0 = (int)fx0, iy0 = (int)fy0;
            int ix1 = min(ix0 + 1, 127), iy1 = min(iy0 + 1, 127);
            float wx = px - fx0, wy = py - fy0;
            float v00 = g_loi[(size_t)(iy0 * 128 + ix0) * 128 + ch];
            float v01 = g_loi[(size_t)(iy0 * 128 + ix1) * 128 + ch];
            float v10 = g_loi[(size_t)(iy1 * 128 + ix0) * 128 + ch];
            float v11 = g_loi[(size_t)(iy1 * 128 + ix1) * 128 + ch];
            float v = v00 * (1.0f - wx) * (1.0f - wy) + v01 * wx * (1.0f - wy)
                    + v10 * (1.0f - wx) * wy + v11 * wx * wy;
            mx = ((s & 3) == 0) ? v : fmaxf(mx, v);
            if ((s & 3) == 3) g_bufA[(size_t)m * 1024 + ch * 8 + (s >> 2)] = mx;
        }
    }
}

// ---------------- stage 9: MLP GEMM  out[m][o] = relu(sum_c A[m][c]*Wm[o][c] + bias[o]) ----------------
__global__ void k_mlp_gemm(const float* __restrict__ A, const float* __restrict__ Wm,
                           const float* __restrict__ bias, float* __restrict__ Out) {
    int M = g_count;
    int mt = blockIdx.x;
    int ot = blockIdx.y;
    if (mt * 128 >= M) return;
    __shared__ float As[16][130];
    __shared__ float Bs[16][130];
    float acc[8][8];
    #pragma unroll
    for (int r = 0; r < 8; r++)
        #pragma unroll
        for (int j = 0; j < 8; j++) acc[r][j] = 0.0f;
    int tid = threadIdx.x;
    int tx = tid & 15, ty = tid >> 4;
    for (int k0 = 0; k0 < 1024; k0 += 16) {
        #pragma unroll
        for (int q = 0; q < 2; q++) {
            int f = tid + q * 256;
            int row = f >> 2;
            int c4 = (f & 3) * 4;
            float4 va = *(const float4*)&A[(size_t)(mt * 128 + row) * 1024 + k0 + c4];
            As[c4 + 0][row] = va.x; As[c4 + 1][row] = va.y;
            As[c4 + 2][row] = va.z; As[c4 + 3][row] = va.w;
            float4 vb = *(const float4*)&Wm[(size_t)(ot * 128 + row) * 1024 + k0 + c4];
            Bs[c4 + 0][row] = vb.x; Bs[c4 + 1][row] = vb.y;
            Bs[c4 + 2][row] = vb.z; Bs[c4 + 3][row] = vb.w;
        }
        __syncthreads();
        #pragma unroll
        for (int kc = 0; kc < 16; kc++) {
            float a[8], b[8];
            #pragma unroll
            for (int r = 0; r < 8; r++) a[r] = As[kc][ty + 16 * r];
            #pragma unroll
            for (int j = 0; j < 8; j++) b[j] = Bs[kc][tx + 16 * j];
            #pragma unroll
            for (int r = 0; r < 8; r++)
                #pragma unroll
                for (int j = 0; j < 8; j++) acc[r][j] += a[r] * b[j];
        }
        __syncthreads();
    }
    #pragma unroll
    for (int r = 0; r < 8; r++) {
        int m = mt * 128 + ty + 16 * r;
        if (m < M) {
            #pragma unroll
            for (int j = 0; j < 8; j++) {
                int o = ot * 128 + tx + 16 * j;
                float v = acc[r][j] + bias[o];
                Out[(size_t)m * 1024 + o] = fmaxf(v, 0.0f);
            }
        }
    }
}

// ---------------- stage 10: final dot + sigmoid ----------------
__global__ void k_final(const float* __restrict__ h2, const float* __restrict__ w3,
                        const float* __restrict__ b3, float* __restrict__ dout) {
    int M = g_count;
    int gtid = blockIdx.x * blockDim.x + threadIdx.x;
    int warp = gtid >> 5;
    int lane = threadIdx.x & 31;
    int nwarps = (gridDim.x * blockDim.x) >> 5;
    for (int m = warp; m < M; m += nwarps) {
        float acc = 0.0f;
        #pragma unroll 8
        for (int c = lane; c < 1024; c += 32)
            acc += h2[(size_t)m * 1024 + c] * w3[c];
        #pragma unroll
        for (int o = 16; o > 0; o >>= 1) acc += __shfl_xor_sync(0xFFFFFFFFu, acc, o);
        if (lane == 0)
            dout[4 * NLINES + m] = 1.0f / (1.0f + expf(-(acc + b3[0])));
    }
}

// ---------------- launch ----------------
extern "C" void kernel_launch(void* const* d_in, const int* in_sizes, int n_in,
                              void* d_out, int out_size) {
    const float* features = (const float*)d_in[0];
    const float* heatmaps = (const float*)d_in[1];
    const float* fc1_w    = (const float*)d_in[2];
    const float* fc1_b    = (const float*)d_in[3];
    const float* w1       = (const float*)d_in[4];
    const float* b1       = (const float*)d_in[5];
    const float* w2       = (const float*)d_in[6];
    const float* b2       = (const float*)d_in[7];
    const float* w3       = (const float*)d_in[8];
    const float* b3       = (const float*)d_in[9];
    float* dout = (float*)d_out;

    void *p_cand, *p_ccount, *p_bitmap, *p_count;
    cudaGetSymbolAddress(&p_cand,   g_cand);
    cudaGetSymbolAddress(&p_ccount, g_ccount);
    cudaGetSymbolAddress(&p_bitmap, g_bitmap);
    cudaGetSymbolAddress(&p_count,  g_count);
    (void)in_sizes; (void)n_in;

    cudaMemsetAsync(p_cand,   0, sizeof(unsigned long long) * 4096);
    cudaMemsetAsync(p_ccount, 0, sizeof(int));
    cudaMemsetAsync(p_bitmap, 0, sizeof(unsigned int) * NBMW);
    cudaMemsetAsync(p_count,  0, sizeof(int));
    cudaMemsetAsync(d_out,    0, (size_t)out_size * sizeof(float));

    k_jloc<<<64, 256>>>(heatmaps);
    k_nms<<<64, 256>>>();
    k_cand<<<64, 256>>>();
    k_topk<<<1, 1024>>>(heatmaps);
    k_match<<<192, 256>>>(heatmaps);
    k_compact<<<1, 1024>>>(dout);

    k_tr<<<128, 256>>>(fc1_w);
    k_loi<<<128, 256>>>(features, fc1_b);
    k_sample<<<512, 128>>>(dout);

    float* A = nullptr; float* B = nullptr;
    cudaGetSymbolAddress((void**)&A, g_bufA);
    cudaGetSymbolAddress((void**)&B, g_bufB);

    dim3 gg(351, 8);
    k_mlp_gemm<<<gg, 256>>>(A, w1, b1, B);
    k_mlp_gemm<<<gg, 256>>>(B, w2, b2, A);
    k_final<<<256, 128>>>(A, w3, b3, dout);
}

// round 5
// speedup vs baseline: 1.8797x; 1.8797x over previous
#include <cuda_runtime.h>
#include <math.h>

#define HW      16384
#define KJ      300
#define NLINES  49152
#define NBMW    2816            // 2816*32 = 90112 >= 90000 bits
#define MPAD    44928           // ceil(44850/128)*128
#define PI_F    3.14159265358979323846f

// ---------------- scratch (static device memory; no allocations) ----------------
__device__ float               g_jloc[HW];
__device__ float               g_nms[HW];
__device__ unsigned long long  g_cand[4096];
__device__ int                 g_ccount;
__device__ float               g_junc[2 * KJ];
__device__ unsigned int        g_bitmap[NBMW];
__device__ int                 g_count;
__device__ float               g_fc1t[256 * 128];
__device__ __align__(128) float g_loi[(size_t)HW * 128];      // [pixel][channel]
__device__ __align__(128) float g_bufA[(size_t)MPAD * 1024];  // feats -> h2
__device__ __align__(128) float g_bufB[(size_t)MPAD * 1024];  // h1

__device__ __forceinline__ float sigm(float x) { return 1.0f / (1.0f + expf(-x)); }

// ---------------- stage 1: jloc = softmax(ch5,ch6)[1] ----------------
__global__ void k_jloc(const float* __restrict__ heat) {
    int i = blockIdx.x * blockDim.x + threadIdx.x;
    if (i < HW) g_jloc[i] = 1.0f / (1.0f + expf(heat[5 * HW + i] - heat[6 * HW + i]));
}

// ---------------- stage 2: 3x3 NMS ----------------
__global__ void k_nms(void) {
    int i = blockIdx.x * blockDim.x + threadIdx.x;
    if (i >= HW) return;
    int y = i >> 7, x = i & 127;
    float m = -1e30f;
    for (int dy = -1; dy <= 1; dy++) {
        int yy = y + dy; if ((unsigned)yy >= 128u) continue;
        for (int dx = -1; dx <= 1; dx++) {
            int xx = x + dx; if ((unsigned)xx >= 128u) continue;
            m = fmaxf(m, g_jloc[yy * 128 + xx]);
        }
    }
    float v = g_jloc[i];
    g_nms[i] = (v == m) ? v : 0.0f;
}

// ---------------- stage 3: gather nonzero candidates ----------------
// 3x3 strict local maxima are non-adjacent -> at most 64*64 = 4096 of them.
__global__ void k_cand(void) {
    int i = blockIdx.x * blockDim.x + threadIdx.x;
    if (i >= HW) return;
    float v = g_nms[i];
    if (v > 0.0f) {
        int p = atomicAdd(&g_ccount, 1);
        if (p < 4096) {
            unsigned long long key =
                ((unsigned long long)__float_as_uint(v) << 32) |
                (unsigned long long)(0xFFFFFFFFu - (unsigned)i);   // ties: lower idx first
            g_cand[p] = key;
        }
    }
}

// ---------------- stage 4: bitonic sort (desc) + junction coords ----------------
__global__ void k_topk(const float* __restrict__ heat) {
    __shared__ unsigned long long s[4096];
    int tid = threadIdx.x;
    for (int q = 0; q < 4; q++) s[q * 1024 + tid] = g_cand[q * 1024 + tid];
    __syncthreads();
    for (int k = 2; k <= 4096; k <<= 1) {
        for (int j = k >> 1; j > 0; j >>= 1) {
            for (int q = 0; q < 4; q++) {
                int i = q * 1024 + tid;
                int ixj = i ^ j;
                if (ixj > i) {
                    unsigned long long a = s[i], b = s[ixj];
                    bool descSeg = (i & k) == 0;
                    bool sw = descSeg ? (a < b) : (a > b);
                    if (sw) { s[i] = b; s[ixj] = a; }
                }
            }
            __syncthreads();
        }
    }
    if (tid < KJ) {
        unsigned long long key = s[tid];
        float v = __uint_as_float((unsigned)(key >> 32));
        if (v > 0.008f) {
            unsigned pix = 0xFFFFFFFFu - (unsigned)(key & 0xFFFFFFFFu);
            float x = (float)(pix & 127u), y = (float)(pix >> 7);
            g_junc[2 * tid + 0] = x + sigm(heat[7 * HW + pix]);
            g_junc[2 * tid + 1] = y + sigm(heat[8 * HW + pix]);
        } else {
            g_junc[2 * tid + 0] = 1e6f;
            g_junc[2 * tid + 1] = 1e6f;
        }
    }
}

// ---------------- stage 5: HAFM decode + junction matching + id bitmap ----------------
__global__ void k_match(const float* __restrict__ heat) {
    __shared__ float sj[2 * KJ];
    for (int i = threadIdx.x; i < 2 * KJ; i += blockDim.x) sj[i] = g_junc[i];
    __syncthreads();
    int n = blockIdx.x * blockDim.x + threadIdx.x;
    if (n >= NLINES) return;
    int ch = n >> 14;
    int pix = n & (HW - 1);
    float x0 = (float)(pix & 127), y0 = (float)(pix >> 7);
    float a0   = sigm(heat[0 * HW + pix]);
    float a1   = sigm(heat[1 * HW + pix]);
    float a2   = sigm(heat[2 * HW + pix]);
    float dist = sigm(heat[3 * HW + pix]);
    float bias = sigm(heat[4 * HW + pix]);
    float d = dist + bias * (float)(ch - 1);
    d = fminf(fmaxf(d, 0.0f), 1.0f);
    float ang0 = (a0 - 0.5f) * PI_F * 2.0f;
    float c0 = cosf(ang0), s0 = sinf(ang0);
    float t1 =  tanf(a1 * (PI_F * 0.5f));
    float t2 = -tanf(a2 * (PI_F * 0.5f));
    float e1x = fminf(fmaxf((c0 - s0 * t1) * d * 5.0f + x0, 0.0f), 127.0f);
    float e1y = fminf(fmaxf((s0 + c0 * t1) * d * 5.0f + y0, 0.0f), 127.0f);
    float e2x = fminf(fmaxf((c0 - s0 * t2) * d * 5.0f + x0, 0.0f), 127.0f);
    float e2y = fminf(fmaxf((s0 + c0 * t2) * d * 5.0f + y0, 0.0f), 127.0f);

    int j1 = 0, j2 = 0;
    float m1 = 3.4e38f, m2 = 3.4e38f;
    #pragma unroll 4
    for (int k = 0; k < KJ; k++) {
        float jx = sj[2 * k], jy = sj[2 * k + 1];
        float dx = jx - e1x, dy = jy - e1y;
        float dd = dx * dx + dy * dy;
        if (dd < m1) { m1 = dd; j1 = k; }
        dx = jx - e2x; dy = jy - e2y;
        dd = dx * dx + dy * dy;
        if (dd < m2) { m2 = dd; j2 = k; }
    }
    int lo = min(j1, j2), hi = max(j1, j2);
    if (lo < hi) {
        int id = lo * KJ + hi;
        atomicOr(&g_bitmap[id >> 5], 1u << (id & 31));
    }
}

// ---------------- stage 6: ordered bitmap compaction -> sorted unique ids ----------------
__global__ void k_compact(float* __restrict__ dout) {
    __shared__ int sc[1024];
    int tid = threadIdx.x;
    int base = tid * 3;
    unsigned w[3] = {0u, 0u, 0u};
    int c = 0;
    #pragma unroll
    for (int q = 0; q < 3; q++) {
        int wi = base + q;
        if (wi < NBMW) { w[q] = g_bitmap[wi]; c += __popc(w[q]); }
    }
    sc[tid] = c;
    __syncthreads();
    for (int off = 1; off < 1024; off <<= 1) {
        int v = 0;
        if (tid >= off) v = sc[tid - off];
        __syncthreads();
        if (tid >= off) sc[tid] += v;
        __syncthreads();
    }
    int pos = sc[tid] - c;     // exclusive prefix
    #pragma unroll
    for (int q = 0; q < 3; q++) {
        unsigned ww = w[q];
        int wbase = (base + q) * 32;
        while (ww) {
            int b = __ffs(ww) - 1;
            ww &= ww - 1;
            int id = wbase + b;
            int lo = id / KJ, hi = id - lo * KJ;
            dout[pos * 4 + 0] = g_junc[2 * lo + 0];
            dout[pos * 4 + 1] = g_junc[2 * lo + 1];
            dout[pos * 4 + 2] = g_junc[2 * hi + 0];
            dout[pos * 4 + 3] = g_junc[2 * hi + 1];
            pos++;
        }
    }
    if (tid == 1023) g_count = sc[1023];
}

// ---------------- stage 7a: transpose fc1_w -> [c][o] ----------------
__global__ void k_tr(const float* __restrict__ fc1w) {
    int i = blockIdx.x * blockDim.x + threadIdx.x;   // i = c*128 + o
    if (i < 256 * 128) {
        int cc = i >> 7, o = i & 127;
        g_fc1t[i] = fc1w[o * 256 + cc];
    }
}

// ---------------- stage 7b: LOI GEMM  loi[p][o] = sum_c feat[c][p]*w[o][c] + b[o] ----------------
__global__ void k_loi(const float* __restrict__ feat, const float* __restrict__ fc1b) {
    __shared__ float As[8][128];   // [kc][p]
    __shared__ float Bs[8][128];   // [kc][o]
    float acc[8][8];
    #pragma unroll
    for (int r = 0; r < 8; r++)
        #pragma unroll
        for (int j = 0; j < 8; j++) acc[r][j] = 0.0f;
    int tid = threadIdx.x;
    int tx = tid & 15, ty = tid >> 4;
    int p0 = blockIdx.x * 128;
    for (int c0 = 0; c0 < 256; c0 += 8) {
        #pragma unroll
        for (int q = 0; q < 4; q++) {
            int idx = tid + q * 256;
            int kc = idx >> 7, col = idx & 127;
            As[kc][col] = feat[(size_t)(c0 + kc) * HW + p0 + col];
            Bs[kc][col] = g_fc1t[(c0 + kc) * 128 + col];
        }
        __syncthreads();
        #pragma unroll
        for (int kc = 0; kc < 8; kc++) {
            float a[8], b[8];
            #pragma unroll
            for (int r = 0; r < 8; r++) a[r] = As[kc][ty + 16 * r];
            #pragma unroll
            for (int j = 0; j < 8; j++) b[j] = Bs[kc][tx + 16 * j];
            #pragma unroll
            for (int r = 0; r < 8; r++)
                #pragma unroll
                for (int j = 0; j < 8; j++) acc[r][j] += a[r] * b[j];
        }
        __syncthreads();
    }
    #pragma unroll
    for (int r = 0; r < 8; r++) {
        int p = p0 + ty + 16 * r;
        #pragma unroll
        for (int j = 0; j < 8; j++) {
            int o = tx + 16 * j;
            g_loi[(size_t)p * 128 + o] = acc[r][j] + fc1b[o];
        }
    }
}

// ---------------- stage 8: bilinear sampling + maxpool4 -> feats[m][1024] ----------------
__global__ void k_sample(const float* __restrict__ dout) {
    int M = g_count;
    int ch = threadIdx.x;      // 128 threads, one channel each
    for (int m = blockIdx.x; m < M; m += gridDim.x) {
        float x1 = dout[m * 4 + 0], y1 = dout[m * 4 + 1];
        float x2 = dout[m * 4 + 2], y2 = dout[m * 4 + 3];
        float mx = -3.4e38f;
        #pragma unroll 4
        for (int s = 0; s < 32; s++) {
            float t = (float)s / 31.0f;
            float px = x1 * t + x2 * (1.0f - t);
            float py = y1 * t + y2 * (1.0f - t);
            px = fminf(fmaxf(px, 0.0f), 127.0f);
            py = fminf(fmaxf(py, 0.0f), 127.0f);
            float fx0 = floorf(px), fy0 = floorf(py);
            int ix0 = (int)fx0, iy0 = (int)fy0;
            int ix1 = min(ix0 + 1, 127), iy1 = min(iy0 + 1, 127);
            float wx = px - fx0, wy = py - fy0;
            float v00 = g_loi[(size_t)(iy0 * 128 + ix0) * 128 + ch];
            float v01 = g_loi[(size_t)(iy0 * 128 + ix1) * 128 + ch];
            float v10 = g_loi[(size_t)(iy1 * 128 + ix0) * 128 + ch];
            float v11 = g_loi[(size_t)(iy1 * 128 + ix1) * 128 + ch];
            float v = v00 * (1.0f - wx) * (1.0f - wy) + v01 * wx * (1.0f - wy)
                    + v10 * (1.0f - wx) * wy + v11 * wx * wy;
            mx = ((s & 3) == 0) ? v : fmaxf(mx, v);
            if ((s & 3) == 3) g_bufA[(size_t)m * 1024 + ch * 8 + (s >> 2)] = mx;
        }
    }
}

// ---------------- stage 9: MLP GEMM via tf32 mma.sync tensor cores ----------------
// Out[m][o] = relu(sum_k A[m][k] * Wm[o][k] + bias[o]); A row-major [m,k],
// Wm row-major [o,k] == col-major k x n as mma's B operand.
__global__ void __launch_bounds__(256, 1)
k_mlp_mma(const float* __restrict__ A, const float* __restrict__ Wm,
          const float* __restrict__ bias, float* __restrict__ Out) {
    int M = g_count;
    int mt = blockIdx.x, ot = blockIdx.y;
    if (mt * 128 >= M) return;

    __shared__ float As[128][36];   // [m][k]  pad->conflict-free frag loads
    __shared__ float Bs[128][36];   // [n][k]

    int tid  = threadIdx.x;
    int lane = tid & 31, wid = tid >> 5;
    int wm = (wid >> 2) * 64;       // warp m-base: 0 / 64
    int wn = (wid & 3) * 32;        // warp n-base: 0..96
    int g  = lane >> 2, tg = lane & 3;

    float c[4][4][4];
    #pragma unroll
    for (int mi = 0; mi < 4; mi++)
        #pragma unroll
        for (int ni = 0; ni < 4; ni++)
            #pragma unroll
            for (int r = 0; r < 4; r++) c[mi][ni][r] = 0.0f;

    const float* Aptr = A  + (size_t)(mt * 128) * 1024;
    const float* Bptr = Wm + (size_t)(ot * 128) * 1024;

    float4 pa[4], pb[4];
    #pragma unroll
    for (int q = 0; q < 4; q++) {
        int f = tid + q * 256;
        int row = f >> 3, c4 = (f & 7) * 4;
        pa[q] = *(const float4*)&Aptr[(size_t)row * 1024 + c4];
        pb[q] = *(const float4*)&Bptr[(size_t)row * 1024 + c4];
    }

    for (int kc = 0; kc < 32; kc++) {
        #pragma unroll
        for (int q = 0; q < 4; q++) {
            int f = tid + q * 256;
            int row = f >> 3, c4 = (f & 7) * 4;
            *(float4*)&As[row][c4] = pa[q];
            *(float4*)&Bs[row][c4] = pb[q];
        }
        __syncthreads();
        if (kc < 31) {
            int k0 = (kc + 1) * 32;
            #pragma unroll
            for (int q = 0; q < 4; q++) {
                int f = tid + q * 256;
                int row = f >> 3, c4 = (f & 7) * 4;
                pa[q] = *(const float4*)&Aptr[(size_t)row * 1024 + k0 + c4];
                pb[q] = *(const float4*)&Bptr[(size_t)row * 1024 + k0 + c4];
            }
        }
        #pragma unroll
        for (int kk = 0; kk < 32; kk += 8) {
            unsigned a[4][4], b[4][2];
            #pragma unroll
            for (int mi = 0; mi < 4; mi++) {
                int r0 = wm + mi * 16 + g;
                a[mi][0] = __float_as_uint(As[r0][kk + tg]);
                a[mi][1] = __float_as_uint(As[r0 + 8][kk + tg]);
                a[mi][2] = __float_as_uint(As[r0][kk + tg + 4]);
                a[mi][3] = __float_as_uint(As[r0 + 8][kk + tg + 4]);
            }
            #pragma unroll
            for (int ni = 0; ni < 4; ni++) {
                int n0 = wn + ni * 8 + g;
                b[ni][0] = __float_as_uint(Bs[n0][kk + tg]);
                b[ni][1] = __float_as_uint(Bs[n0][kk + tg + 4]);
            }
            #pragma unroll
            for (int mi = 0; mi < 4; mi++)
                #pragma unroll
                for (int ni = 0; ni < 4; ni++)
                    asm volatile(
                        "mma.sync.aligned.m16n8k8.row.col.f32.tf32.tf32.f32 "
                        "{%0,%1,%2,%3}, {%4,%5,%6,%7}, {%8,%9}, {%0,%1,%2,%3};"
                        : "+f"(c[mi][ni][0]), "+f"(c[mi][ni][1]),
                          "+f"(c[mi][ni][2]), "+f"(c[mi][ni][3])
                        : "r"(a[mi][0]), "r"(a[mi][1]), "r"(a[mi][2]), "r"(a[mi][3]),
                          "r"(b[ni][0]), "r"(b[ni][1]));
        }
        __syncthreads();
    }

    // epilogue: bias + relu
    #pragma unroll
    for (int mi = 0; mi < 4; mi++) {
        int m0 = mt * 128 + wm + mi * 16 + g;
        #pragma unroll
        for (int ni = 0; ni < 4; ni++) {
            int o = ot * 128 + wn + ni * 8 + 2 * tg;
            float bv0 = bias[o], bv1 = bias[o + 1];
            if (m0 < M) {
                float2 v = make_float2(fmaxf(c[mi][ni][0] + bv0, 0.0f),
                                       fmaxf(c[mi][ni][1] + bv1, 0.0f));
                *(float2*)&Out[(size_t)m0 * 1024 + o] = v;
            }
            if (m0 + 8 < M) {
                float2 v = make_float2(fmaxf(c[mi][ni][2] + bv0, 0.0f),
                                       fmaxf(c[mi][ni][3] + bv1, 0.0f));
                *(float2*)&Out[(size_t)(m0 + 8) * 1024 + o] = v;
            }
        }
    }
}

// ---------------- stage 10: final dot + sigmoid ----------------
__global__ void k_final(const float* __restrict__ h2, const float* __restrict__ w3,
                        const float* __restrict__ b3, float* __restrict__ dout) {
    int M = g_count;
    int gtid = blockIdx.x * blockDim.x + threadIdx.x;
    int warp = gtid >> 5;
    int lane = threadIdx.x & 31;
    int nwarps = (gridDim.x * blockDim.x) >> 5;
    for (int m = warp; m < M; m += nwarps) {
        float acc = 0.0f;
        #pragma unroll 8
        for (int c = lane; c < 1024; c += 32)
            acc += h2[(size_t)m * 1024 + c] * w3[c];
        #pragma unroll
        for (int o = 16; o > 0; o >>= 1) acc += __shfl_xor_sync(0xFFFFFFFFu, acc, o);
        if (lane == 0)
            dout[4 * NLINES + m] = 1.0f / (1.0f + expf(-(acc + b3[0])));
    }
}

// ---------------- launch ----------------
extern "C" void kernel_launch(void* const* d_in, const int* in_sizes, int n_in,
                              void* d_out, int out_size) {
    const float* features = (const float*)d_in[0];
    const float* heatmaps = (const float*)d_in[1];
    const float* fc1_w    = (const float*)d_in[2];
    const float* fc1_b    = (const float*)d_in[3];
    const float* w1       = (const float*)d_in[4];
    const float* b1       = (const float*)d_in[5];
    const float* w2       = (const float*)d_in[6];
    const float* b2       = (const float*)d_in[7];
    const float* w3       = (const float*)d_in[8];
    const float* b3       = (const float*)d_in[9];
    float* dout = (float*)d_out;

    void *p_cand, *p_ccount, *p_bitmap, *p_count;
    cudaGetSymbolAddress(&p_cand,   g_cand);
    cudaGetSymbolAddress(&p_ccount, g_ccount);
    cudaGetSymbolAddress(&p_bitmap, g_bitmap);
    cudaGetSymbolAddress(&p_count,  g_count);
    (void)in_sizes; (void)n_in;

    cudaMemsetAsync(p_cand,   0, sizeof(unsigned long long) * 4096);
    cudaMemsetAsync(p_ccount, 0, sizeof(int));
    cudaMemsetAsync(p_bitmap, 0, sizeof(unsigned int) * NBMW);
    cudaMemsetAsync(p_count,  0, sizeof(int));
    cudaMemsetAsync(d_out,    0, (size_t)out_size * sizeof(float));

    k_jloc<<<64, 256>>>(heatmaps);
    k_nms<<<64, 256>>>();
    k_cand<<<64, 256>>>();
    k_topk<<<1, 1024>>>(heatmaps);
    k_match<<<192, 256>>>(heatmaps);
    k_compact<<<1, 1024>>>(dout);

    k_tr<<<128, 256>>>(fc1_w);
    k_loi<<<128, 256>>>(features, fc1_b);
    k_sample<<<512, 128>>>(dout);

    float* A = nullptr; float* B = nullptr;
    cudaGetSymbolAddress((void**)&A, g_bufA);
    cudaGetSymbolAddress((void**)&B, g_bufB);

    dim3 gg(351, 8);
    k_mlp_mma<<<gg, 256>>>(A, w1, b1, B);
    k_mlp_mma<<<gg, 256>>>(B, w2, b2, A);
    k_final<<<256, 128>>>(A, w3, b3, dout);
}

// round 6
// speedup vs baseline: 2.3407x; 1.2452x over previous
#include <cuda_runtime.h>
#include <math.h>

#define HW      16384
#define KJ      300
#define NLINES  49152
#define NBMW    2816            // 2816*32 = 90112 >= 90000 bits
#define MPAD    44928           // ceil(44850/128)*128
#define PI_F    3.14159265358979323846f

// ---------------- scratch (static device memory; no allocations) ----------------
__device__ unsigned long long  g_cand[4096];
__device__ int                 g_ccount;
__device__ float               g_junc[2 * KJ];
__device__ unsigned int        g_bitmap[NBMW];
__device__ int                 g_count;
__device__ __align__(128) float g_loi[(size_t)HW * 128];      // [pixel][channel]
__device__ __align__(128) float g_bufA[(size_t)MPAD * 1024];  // feats -> h2
__device__ __align__(128) float g_bufB[(size_t)MPAD * 1024];  // h1

__device__ __forceinline__ float sigm(float x) { return 1.0f / (1.0f + expf(-x)); }

__device__ __forceinline__ void cp16(void* smem, const void* gptr) {
    unsigned s = (unsigned)__cvta_generic_to_shared(smem);
    asm volatile("cp.async.cg.shared.global [%0], [%1], 16;" :: "r"(s), "l"(gptr));
}
__device__ __forceinline__ void cp_commit() { asm volatile("cp.async.commit_group;"); }
__device__ __forceinline__ void cp_wait0()  { asm volatile("cp.async.wait_group 0;"); }

// ---------------- stage 1 (fused): jloc + 3x3 NMS + candidate gather ----------------
__device__ __forceinline__ float jl(const float* __restrict__ heat, int p) {
    return 1.0f / (1.0f + expf(heat[5 * HW + p] - heat[6 * HW + p]));
}
__global__ void k_prop(const float* __restrict__ heat) {
    int i = blockIdx.x * blockDim.x + threadIdx.x;
    if (i >= HW) return;
    int y = i >> 7, x = i & 127;
    float v = jl(heat, i);
    float m = v;
    for (int dy = -1; dy <= 1; dy++) {
        int yy = y + dy; if ((unsigned)yy >= 128u) continue;
        for (int dx = -1; dx <= 1; dx++) {
            if (dy == 0 && dx == 0) continue;
            int xx = x + dx; if ((unsigned)xx >= 128u) continue;
            m = fmaxf(m, jl(heat, yy * 128 + xx));
        }
    }
    if (v == m && v > 0.0f) {
        int p = atomicAdd(&g_ccount, 1);
        if (p < 4096) {
            unsigned long long key =
                ((unsigned long long)__float_as_uint(v) << 32) |
                (unsigned long long)(0xFFFFFFFFu - (unsigned)i);   // ties: lower idx first
            g_cand[p] = key;
        }
    }
}

// ---------------- stage 2: histogram select + small bitonic sort + junction coords ----
__global__ void k_topk_sel(const float* __restrict__ heat) {
    __shared__ unsigned long long sbuf[4096];   // aliased as 8192-bin u32 histogram
    __shared__ int sc[1024];
    __shared__ int sB, sTot, sPos;
    unsigned int* hist = (unsigned int*)sbuf;
    int t = threadIdx.x;

    #pragma unroll
    for (int q = 0; q < 8; q++) hist[q * 1024 + t] = 0u;
    if (t == 0) { sPos = 0; sB = 0; sTot = 0; }
    __syncthreads();

    unsigned long long kk[4];
    #pragma unroll
    for (int q = 0; q < 4; q++) {
        unsigned long long key = g_cand[q * 1024 + t];
        kk[q] = key;
        if (key >> 32)
            atomicAdd(&hist[(int)((key >> 50) & 0x1FFF)], 1u);
    }
    __syncthreads();

    // group suffix sums (8 bins per thread)
    int gs = 0;
    #pragma unroll
    for (int b = 0; b < 8; b++) gs += hist[t * 8 + b];
    sc[t] = gs;
    __syncthreads();
    for (int off = 1; off < 1024; off <<= 1) {
        int v = (t + off < 1024) ? sc[t + off] : 0;
        __syncthreads();
        sc[t] += v;
        __syncthreads();
    }
    int sufN = (t < 1023) ? sc[t + 1] : 0;
    if (t == 0 && sc[0] < KJ) { sB = 0; sTot = sc[0]; }
    if (sc[0] >= KJ && sc[t] >= KJ && sufN < KJ) {
        int run = sufN;
        for (int b = t * 8 + 7; b >= t * 8; b--) {
            run += hist[b];
            if (run >= KJ) { sB = b; sTot = run; break; }
        }
    }
    __syncthreads();
    int B = sB, total = sTot;

    // collect survivors (hist no longer read; sbuf reuse is safe after the sync)
    #pragma unroll
    for (int q = 0; q < 4; q++) {
        unsigned long long key = kk[q];
        if ((key >> 32) && (int)((key >> 50) & 0x1FFF) >= B) {
            int p = atomicAdd(&sPos, 1);
            sbuf[p] = key;
        }
    }
    __syncthreads();

    int n = (total <= 512) ? 512 : (total <= 1024) ? 1024 : (total <= 2048) ? 2048 : 4096;
    for (int i = total + t; i < n; i += 1024) sbuf[i] = 0ULL;
    __syncthreads();

    for (int k = 2; k <= n; k <<= 1) {
        for (int j = k >> 1; j > 0; j >>= 1) {
            for (int i = t; i < n; i += 1024) {
                int ixj = i ^ j;
                if (ixj > i) {
                    unsigned long long a = sbuf[i], b = sbuf[ixj];
                    bool descSeg = (i & k) == 0;
                    if (descSeg ? (a < b) : (a > b)) { sbuf[i] = b; sbuf[ixj] = a; }
                }
            }
            __syncthreads();
        }
    }

    if (t < KJ) {
        unsigned long long key = sbuf[t];
        float v = __uint_as_float((unsigned)(key >> 32));
        if (v > 0.008f) {
            unsigned pix = 0xFFFFFFFFu - (unsigned)(key & 0xFFFFFFFFu);
            float x = (float)(pix & 127u), y = (float)(pix >> 7);
            g_junc[2 * t + 0] = x + sigm(heat[7 * HW + pix]);
            g_junc[2 * t + 1] = y + sigm(heat[8 * HW + pix]);
        } else {
            g_junc[2 * t + 0] = 1e6f;
            g_junc[2 * t + 1] = 1e6f;
        }
    }
}

// ---------------- stage 3: HAFM decode + junction matching + id bitmap ----------------
__global__ void k_match(const float* __restrict__ heat) {
    __shared__ float sj[2 * KJ];
    for (int i = threadIdx.x; i < 2 * KJ; i += blockDim.x) sj[i] = g_junc[i];
    __syncthreads();
    int n = blockIdx.x * blockDim.x + threadIdx.x;
    if (n >= NLINES) return;
    int ch = n >> 14;
    int pix = n & (HW - 1);
    float x0 = (float)(pix & 127), y0 = (float)(pix >> 7);
    float a0   = sigm(heat[0 * HW + pix]);
    float a1   = sigm(heat[1 * HW + pix]);
    float a2   = sigm(heat[2 * HW + pix]);
    float dist = sigm(heat[3 * HW + pix]);
    float bias = sigm(heat[4 * HW + pix]);
    float d = dist + bias * (float)(ch - 1);
    d = fminf(fmaxf(d, 0.0f), 1.0f);
    float ang0 = (a0 - 0.5f) * PI_F * 2.0f;
    float c0 = cosf(ang0), s0 = sinf(ang0);
    float t1 =  tanf(a1 * (PI_F * 0.5f));
    float t2 = -tanf(a2 * (PI_F * 0.5f));
    float e1x = fminf(fmaxf((c0 - s0 * t1) * d * 5.0f + x0, 0.0f), 127.0f);
    float e1y = fminf(fmaxf((s0 + c0 * t1) * d * 5.0f + y0, 0.0f), 127.0f);
    float e2x = fminf(fmaxf((c0 - s0 * t2) * d * 5.0f + x0, 0.0f), 127.0f);
    float e2y = fminf(fmaxf((s0 + c0 * t2) * d * 5.0f + y0, 0.0f), 127.0f);

    int j1 = 0, j2 = 0;
    float m1 = 3.4e38f, m2 = 3.4e38f;
    #pragma unroll 4
    for (int k = 0; k < KJ; k++) {
        float jx = sj[2 * k], jy = sj[2 * k + 1];
        float dx = jx - e1x, dy = jy - e1y;
        float dd = dx * dx + dy * dy;
        if (dd < m1) { m1 = dd; j1 = k; }
        dx = jx - e2x; dy = jy - e2y;
        dd = dx * dx + dy * dy;
        if (dd < m2) { m2 = dd; j2 = k; }
    }
    int lo = min(j1, j2), hi = max(j1, j2);
    if (lo < hi) {
        int id = lo * KJ + hi;
        atomicOr(&g_bitmap[id >> 5], 1u << (id & 31));
    }
}

// ---------------- stage 4: ordered bitmap compaction -> sorted unique ids ----------------
__global__ void k_compact(float* __restrict__ dout) {
    __shared__ int sc[1024];
    int tid = threadIdx.x;
    int base = tid * 3;
    unsigned w[3] = {0u, 0u, 0u};
    int c = 0;
    #pragma unroll
    for (int q = 0; q < 3; q++) {
        int wi = base + q;
        if (wi < NBMW) { w[q] = g_bitmap[wi]; c += __popc(w[q]); }
    }
    sc[tid] = c;
    __syncthreads();
    for (int off = 1; off < 1024; off <<= 1) {
        int v = 0;
        if (tid >= off) v = sc[tid - off];
        __syncthreads();
        if (tid >= off) sc[tid] += v;
        __syncthreads();
    }
    int pos = sc[tid] - c;     // exclusive prefix
    #pragma unroll
    for (int q = 0; q < 3; q++) {
        unsigned ww = w[q];
        int wbase = (base + q) * 32;
        while (ww) {
            int b = __ffs(ww) - 1;
            ww &= ww - 1;
            int id = wbase + b;
            int lo = id / KJ, hi = id - lo * KJ;
            dout[pos * 4 + 0] = g_junc[2 * lo + 0];
            dout[pos * 4 + 1] = g_junc[2 * lo + 1];
            dout[pos * 4 + 2] = g_junc[2 * hi + 0];
            dout[pos * 4 + 3] = g_junc[2 * hi + 1];
            pos++;
        }
    }
    if (tid == 1023) g_count = sc[1023];
}

// ---------------- stage 5: LOI GEMM via tf32 MMA (fused transpose of feat) ----------
// g_loi[p][o] = sum_c feat[c][p] * fc1w[o][c] + fc1b[o]
__global__ void __launch_bounds__(256, 2)
k_loi_mma(const float* __restrict__ feat, const float* __restrict__ fc1w,
          const float* __restrict__ fc1b) {
    __shared__ float As[128][33];   // [p][k]  (transposed feat, pad 33 conflict-free)
    __shared__ float Bs[128][33];   // [o][k]

    int tid  = threadIdx.x;
    int lane = tid & 31, wid = tid >> 5;
    int wm = (wid >> 2) * 64;       // warp p-base
    int wn = (wid & 3) * 32;        // warp o-base
    int g  = lane >> 2, tg = lane & 3;
    int p0 = blockIdx.x * 128;

    float c[4][4][4];
    #pragma unroll
    for (int mi = 0; mi < 4; mi++)
        #pragma unroll
        for (int ni = 0; ni < 4; ni++)
            #pragma unroll
            for (int r = 0; r < 4; r++) c[mi][ni][r] = 0.0f;

    for (int c0 = 0; c0 < 256; c0 += 32) {
        // load + transpose feat tile: As[p][kc] = feat[c0+kc][p0+p]
        #pragma unroll
        for (int q = 0; q < 16; q++) {
            int f = tid + q * 256;
            int kc = f >> 7, p = f & 127;
            As[p][kc] = feat[(size_t)(c0 + kc) * HW + p0 + p];
        }
        // load weights: Bs[o][cc] = fc1w[o][c0+cc]
        #pragma unroll
        for (int q = 0; q < 16; q++) {
            int f = tid + q * 256;
            int cc = f & 31, o = f >> 5;
            Bs[o][cc] = fc1w[(size_t)o * 256 + c0 + cc];
        }
        __syncthreads();
        #pragma unroll
        for (int kk = 0; kk < 32; kk += 8) {
            unsigned a[4][4], b[4][2];
            #pragma unroll
            for (int mi = 0; mi < 4; mi++) {
                int r0 = wm + mi * 16 + g;
                a[mi][0] = __float_as_uint(As[r0][kk + tg]);
                a[mi][1] = __float_as_uint(As[r0 + 8][kk + tg]);
                a[mi][2] = __float_as_uint(As[r0][kk + tg + 4]);
                a[mi][3] = __float_as_uint(As[r0 + 8][kk + tg + 4]);
            }
            #pragma unroll
            for (int ni = 0; ni < 4; ni++) {
                int n0 = wn + ni * 8 + g;
                b[ni][0] = __float_as_uint(Bs[n0][kk + tg]);
                b[ni][1] = __float_as_uint(Bs[n0][kk + tg + 4]);
            }
            #pragma unroll
            for (int mi = 0; mi < 4; mi++)
                #pragma unroll
                for (int ni = 0; ni < 4; ni++)
                    asm volatile(
                        "mma.sync.aligned.m16n8k8.row.col.f32.tf32.tf32.f32 "
                        "{%0,%1,%2,%3}, {%4,%5,%6,%7}, {%8,%9}, {%0,%1,%2,%3};"
                        : "+f"(c[mi][ni][0]), "+f"(c[mi][ni][1]),
                          "+f"(c[mi][ni][2]), "+f"(c[mi][ni][3])
                        : "r"(a[mi][0]), "r"(a[mi][1]), "r"(a[mi][2]), "r"(a[mi][3]),
                          "r"(b[ni][0]), "r"(b[ni][1]));
        }
        __syncthreads();
    }

    #pragma unroll
    for (int mi = 0; mi < 4; mi++) {
        int p = p0 + wm + mi * 16 + g;
        #pragma unroll
        for (int ni = 0; ni < 4; ni++) {
            int o = wn + ni * 8 + 2 * tg;
            float bv0 = fc1b[o], bv1 = fc1b[o + 1];
            *(float2*)&g_loi[(size_t)p * 128 + o] =
                make_float2(c[mi][ni][0] + bv0, c[mi][ni][1] + bv1);
            *(float2*)&g_loi[(size_t)(p + 8) * 128 + o] =
                make_float2(c[mi][ni][2] + bv0, c[mi][ni][3] + bv1);
        }
    }
}

// ---------------- stage 6: bilinear sampling + maxpool4 -> feats[m][1024] ----------------
__global__ void k_sample(const float* __restrict__ dout) {
    int M = g_count;
    int ch = threadIdx.x;      // 128 threads, one channel each
    for (int m = blockIdx.x; m < M; m += gridDim.x) {
        float x1 = dout[m * 4 + 0], y1 = dout[m * 4 + 1];
        float x2 = dout[m * 4 + 2], y2 = dout[m * 4 + 3];
        float mx = -3.4e38f;
        #pragma unroll 4
        for (int s = 0; s < 32; s++) {
            float t = (float)s / 31.0f;
            float px = x1 * t + x2 * (1.0f - t);
            float py = y1 * t + y2 * (1.0f - t);
            px = fminf(fmaxf(px, 0.0f), 127.0f);
            py = fminf(fmaxf(py, 0.0f), 127.0f);
            float fx0 = floorf(px), fy0 = floorf(py);
            int ix0 = (int)fx0, iy0 = (int)fy0;
            int ix1 = min(ix0 + 1, 127), iy1 = min(iy0 + 1, 127);
            float wx = px - fx0, wy = py - fy0;
            float v00 = g_loi[(size_t)(iy0 * 128 + ix0) * 128 + ch];
            float v01 = g_loi[(size_t)(iy0 * 128 + ix1) * 128 + ch];
            float v10 = g_loi[(size_t)(iy1 * 128 + ix0) * 128 + ch];
            float v11 = g_loi[(size_t)(iy1 * 128 + ix1) * 128 + ch];
            float v = v00 * (1.0f - wx) * (1.0f - wy) + v01 * wx * (1.0f - wy)
                    + v10 * (1.0f - wx) * wy + v11 * wx * wy;
            mx = ((s & 3) == 0) ? v : fmaxf(mx, v);
            if ((s & 3) == 3) g_bufA[(size_t)m * 1024 + ch * 8 + (s >> 2)] = mx;
        }
    }
}

// ---------------- stage 7: MLP GEMM via tf32 mma.sync, cp.async, occ=2 ----------------
__global__ void __launch_bounds__(256, 2)
k_mlp_mma(const float* __restrict__ A, const float* __restrict__ Wm,
          const float* __restrict__ bias, float* __restrict__ Out) {
    int M = g_count;
    int mt = blockIdx.x, ot = blockIdx.y;
    if (mt * 128 >= M) return;

    __shared__ float As[128][36];   // [m][k]  pad 36 keeps 16B-aligned rows
    __shared__ float Bs[128][36];   // [n][k]

    int tid  = threadIdx.x;
    int lane = tid & 31, wid = tid >> 5;
    int wm = (wid >> 2) * 64;
    int wn = (wid & 3) * 32;
    int g  = lane >> 2, tg = lane & 3;

    float c[4][4][4];
    #pragma unroll
    for (int mi = 0; mi < 4; mi++)
        #pragma unroll
        for (int ni = 0; ni < 4; ni++)
            #pragma unroll
            for (int r = 0; r < 4; r++) c[mi][ni][r] = 0.0f;

    const float* Aptr = A  + (size_t)(mt * 128) * 1024;
    const float* Bptr = Wm + (size_t)(ot * 128) * 1024;

    // prologue: stage 0
    #pragma unroll
    for (int q = 0; q < 4; q++) {
        int f = tid + q * 256;
        int row = f >> 3, c4 = (f & 7) * 4;
        cp16(&As[row][c4], &Aptr[(size_t)row * 1024 + c4]);
        cp16(&Bs[row][c4], &Bptr[(size_t)row * 1024 + c4]);
    }
    cp_commit();

    for (int kc = 0; kc < 32; kc++) {
        cp_wait0();
        __syncthreads();
        #pragma unroll
        for (int kk = 0; kk < 32; kk += 8) {
            unsigned a[4][4], b[4][2];
            #pragma unroll
            for (int mi = 0; mi < 4; mi++) {
                int r0 = wm + mi * 16 + g;
                a[mi][0] = __float_as_uint(As[r0][kk + tg]);
                a[mi][1] = __float_as_uint(As[r0 + 8][kk + tg]);
                a[mi][2] = __float_as_uint(As[r0][kk + tg + 4]);
                a[mi][3] = __float_as_uint(As[r0 + 8][kk + tg + 4]);
            }
            #pragma unroll
            for (int ni = 0; ni < 4; ni++) {
                int n0 = wn + ni * 8 + g;
                b[ni][0] = __float_as_uint(Bs[n0][kk + tg]);
                b[ni][1] = __float_as_uint(Bs[n0][kk + tg + 4]);
            }
            #pragma unroll
            for (int mi = 0; mi < 4; mi++)
                #pragma unroll
                for (int ni = 0; ni < 4; ni++)
                    asm volatile(
                        "mma.sync.aligned.m16n8k8.row.col.f32.tf32.tf32.f32 "
                        "{%0,%1,%2,%3}, {%4,%5,%6,%7}, {%8,%9}, {%0,%1,%2,%3};"
                        : "+f"(c[mi][ni][0]), "+f"(c[mi][ni][1]),
                          "+f"(c[mi][ni][2]), "+f"(c[mi][ni][3])
                        : "r"(a[mi][0]), "r"(a[mi][1]), "r"(a[mi][2]), "r"(a[mi][3]),
                          "r"(b[ni][0]), "r"(b[ni][1]));
        }
        __syncthreads();
        if (kc < 31) {
            int k0 = (kc + 1) * 32;
            #pragma unroll
            for (int q = 0; q < 4; q++) {
                int f = tid + q * 256;
                int row = f >> 3, c4 = (f & 7) * 4;
                cp16(&As[row][c4], &Aptr[(size_t)row * 1024 + k0 + c4]);
                cp16(&Bs[row][c4], &Bptr[(size_t)row * 1024 + k0 + c4]);
            }
            cp_commit();
        }
    }

    // epilogue: bias + relu
    #pragma unroll
    for (int mi = 0; mi < 4; mi++) {
        int m0 = mt * 128 + wm + mi * 16 + g;
        #pragma unroll
        for (int ni = 0; ni < 4; ni++) {
            int o = ot * 128 + wn + ni * 8 + 2 * tg;
            float bv0 = bias[o], bv1 = bias[o + 1];
            if (m0 < M) {
                float2 v = make_float2(fmaxf(c[mi][ni][0] + bv0, 0.0f),
                                       fmaxf(c[mi][ni][1] + bv1, 0.0f));
                *(float2*)&Out[(size_t)m0 * 1024 + o] = v;
            }
            if (m0 + 8 < M) {
                float2 v = make_float2(fmaxf(c[mi][ni][2] + bv0, 0.0f),
                                       fmaxf(c[mi][ni][3] + bv1, 0.0f));
                *(float2*)&Out[(size_t)(m0 + 8) * 1024 + o] = v;
            }
        }
    }
}

// ---------------- stage 8: final dot + sigmoid ----------------
__global__ void k_final(const float* __restrict__ h2, const float* __restrict__ w3,
                        const float* __restrict__ b3, float* __restrict__ dout) {
    int M = g_count;
    int gtid = blockIdx.x * blockDim.x + threadIdx.x;
    int warp = gtid >> 5;
    int lane = threadIdx.x & 31;
    int nwarps = (gridDim.x * blockDim.x) >> 5;
    for (int m = warp; m < M; m += nwarps) {
        float acc = 0.0f;
        #pragma unroll 8
        for (int c = lane; c < 1024; c += 32)
            acc += h2[(size_t)m * 1024 + c] * w3[c];
        #pragma unroll
        for (int o = 16; o > 0; o >>= 1) acc += __shfl_xor_sync(0xFFFFFFFFu, acc, o);
        if (lane == 0)
            dout[4 * NLINES + m] = 1.0f / (1.0f + expf(-(acc + b3[0])));
    }
}

// ---------------- launch ----------------
extern "C" void kernel_launch(void* const* d_in, const int* in_sizes, int n_in,
                              void* d_out, int out_size) {
    const float* features = (const float*)d_in[0];
    const float* heatmaps = (const float*)d_in[1];
    const float* fc1_w    = (const float*)d_in[2];
    const float* fc1_b    = (const float*)d_in[3];
    const float* w1       = (const float*)d_in[4];
    const float* b1       = (const float*)d_in[5];
    const float* w2       = (const float*)d_in[6];
    const float* b2       = (const float*)d_in[7];
    const float* w3       = (const float*)d_in[8];
    const float* b3       = (const float*)d_in[9];
    float* dout = (float*)d_out;

    void *p_cand, *p_ccount, *p_bitmap, *p_count;
    cudaGetSymbolAddress(&p_cand,   g_cand);
    cudaGetSymbolAddress(&p_ccount, g_ccount);
    cudaGetSymbolAddress(&p_bitmap, g_bitmap);
    cudaGetSymbolAddress(&p_count,  g_count);
    (void)in_sizes; (void)n_in;

    cudaMemsetAsync(p_cand,   0, sizeof(unsigned long long) * 4096);
    cudaMemsetAsync(p_ccount, 0, sizeof(int));
    cudaMemsetAsync(p_bitmap, 0, sizeof(unsigned int) * NBMW);
    cudaMemsetAsync(p_count,  0, sizeof(int));
    cudaMemsetAsync(d_out,    0, (size_t)out_size * sizeof(float));

    k_prop<<<64, 256>>>(heatmaps);
    k_topk_sel<<<1, 1024>>>(heatmaps);
    k_match<<<192, 256>>>(heatmaps);
    k_compact<<<1, 1024>>>(dout);

    k_loi_mma<<<128, 256>>>(features, fc1_w, fc1_b);
    k_sample<<<512, 128>>>(dout);

    float* A = nullptr; float* B = nullptr;
    cudaGetSymbolAddress((void**)&A, g_bufA);
    cudaGetSymbolAddress((void**)&B, g_bufB);

    dim3 gg(351, 8);
    k_mlp_mma<<<gg, 256>>>(A, w1, b1, B);
    k_mlp_mma<<<gg, 256>>>(B, w2, b2, A);
    k_final<<<256, 128>>>(A, w3, b3, dout);
}

// round 7
// speedup vs baseline: 2.5213x; 1.0772x over previous
#include <cuda_runtime.h>
#include <math.h>

#define HW      16384
#define KJ      300
#define NLINES  49152
#define NBMW    2816            // 2816*32 = 90112 >= 90000 bits
#define MPAD    44928           // ceil(44850/128)*128
#define PI_F    3.14159265358979323846f

// ---------------- scratch (static device memory; no allocations) ----------------
__device__ unsigned long long  g_cand[4096];
__device__ int                 g_ctrs[2];     // [0]=cand count, [1]=line count
__device__ float               g_junc[2 * KJ];
__device__ unsigned int        g_bitmap[NBMW];
__device__ __align__(128) float g_loi[(size_t)HW * 128];      // [pixel][channel]
__device__ __align__(128) float g_bufA[(size_t)MPAD * 1024];  // feats -> h2
__device__ __align__(128) float g_bufB[(size_t)MPAD * 1024];  // h1

__device__ __forceinline__ float sigm(float x) { return 1.0f / (1.0f + expf(-x)); }

__device__ __forceinline__ void cp16(void* smem, const void* gptr) {
    unsigned s = (unsigned)__cvta_generic_to_shared(smem);
    asm volatile("cp.async.cg.shared.global [%0], [%1], 16;" :: "r"(s), "l"(gptr));
}
__device__ __forceinline__ void cp_commit() { asm volatile("cp.async.commit_group;"); }
__device__ __forceinline__ void cp_wait1()  { asm volatile("cp.async.wait_group 1;"); }

// ---------------- stage 1 (fused): jloc + 3x3 NMS + candidate gather ----------------
__device__ __forceinline__ float jl(const float* __restrict__ heat, int p) {
    return 1.0f / (1.0f + expf(heat[5 * HW + p] - heat[6 * HW + p]));
}
__global__ void k_prop(const float* __restrict__ heat) {
    int i = blockIdx.x * blockDim.x + threadIdx.x;
    if (i >= HW) return;
    int y = i >> 7, x = i & 127;
    float v = jl(heat, i);
    float m = v;
    for (int dy = -1; dy <= 1; dy++) {
        int yy = y + dy; if ((unsigned)yy >= 128u) continue;
        for (int dx = -1; dx <= 1; dx++) {
            if (dy == 0 && dx == 0) continue;
            int xx = x + dx; if ((unsigned)xx >= 128u) continue;
            m = fmaxf(m, jl(heat, yy * 128 + xx));
        }
    }
    if (v == m && v > 0.0f) {
        int p = atomicAdd(&g_ctrs[0], 1);
        if (p < 4096) {
            unsigned long long key =
                ((unsigned long long)__float_as_uint(v) << 32) |
                (unsigned long long)(0xFFFFFFFFu - (unsigned)i);   // ties: lower idx first
            g_cand[p] = key;
        }
    }
}

// ---------------- stage 2: histogram select + small bitonic sort + junction coords ----
__global__ void k_topk_sel(const float* __restrict__ heat) {
    __shared__ unsigned long long sbuf[4096];   // aliased as 8192-bin u32 histogram
    __shared__ int sc[1024];
    __shared__ int sB, sTot, sPos;
    unsigned int* hist = (unsigned int*)sbuf;
    int t = threadIdx.x;
    int cc = g_ctrs[0];
    if (cc > 4096) cc = 4096;

    #pragma unroll
    for (int q = 0; q < 8; q++) hist[q * 1024 + t] = 0u;
    if (t == 0) { sPos = 0; sB = 0; sTot = 0; }
    __syncthreads();

    unsigned long long kk[4];
    #pragma unroll
    for (int q = 0; q < 4; q++) {
        int idx = q * 1024 + t;
        unsigned long long key = (idx < cc) ? g_cand[idx] : 0ULL;
        kk[q] = key;
        if (key >> 32)
            atomicAdd(&hist[(int)((key >> 50) & 0x1FFF)], 1u);
    }
    __syncthreads();

    // group suffix sums (8 bins per thread)
    int gs = 0;
    #pragma unroll
    for (int b = 0; b < 8; b++) gs += hist[t * 8 + b];
    sc[t] = gs;
    __syncthreads();
    for (int off = 1; off < 1024; off <<= 1) {
        int v = (t + off < 1024) ? sc[t + off] : 0;
        __syncthreads();
        sc[t] += v;
        __syncthreads();
    }
    int sufN = (t < 1023) ? sc[t + 1] : 0;
    if (t == 0 && sc[0] < KJ) { sB = 0; sTot = sc[0]; }
    if (sc[0] >= KJ && sc[t] >= KJ && sufN < KJ) {
        int run = sufN;
        for (int b = t * 8 + 7; b >= t * 8; b--) {
            run += hist[b];
            if (run >= KJ) { sB = b; sTot = run; break; }
        }
    }
    __syncthreads();
    int B = sB, total = sTot;

    // collect survivors (hist no longer read; sbuf reuse is safe after the sync)
    #pragma unroll
    for (int q = 0; q < 4; q++) {
        unsigned long long key = kk[q];
        if ((key >> 32) && (int)((key >> 50) & 0x1FFF) >= B) {
            int p = atomicAdd(&sPos, 1);
            sbuf[p] = key;
        }
    }
    __syncthreads();

    int n = (total <= 512) ? 512 : (total <= 1024) ? 1024 : (total <= 2048) ? 2048 : 4096;
    for (int i = total + t; i < n; i += 1024) sbuf[i] = 0ULL;
    __syncthreads();

    for (int k = 2; k <= n; k <<= 1) {
        for (int j = k >> 1; j > 0; j >>= 1) {
            for (int i = t; i < n; i += 1024) {
                int ixj = i ^ j;
                if (ixj > i) {
                    unsigned long long a = sbuf[i], b = sbuf[ixj];
                    bool descSeg = (i & k) == 0;
                    if (descSeg ? (a < b) : (a > b)) { sbuf[i] = b; sbuf[ixj] = a; }
                }
            }
            __syncthreads();
        }
    }

    if (t < KJ) {
        unsigned long long key = sbuf[t];
        float v = __uint_as_float((unsigned)(key >> 32));
        if (v > 0.008f) {
            unsigned pix = 0xFFFFFFFFu - (unsigned)(key & 0xFFFFFFFFu);
            float x = (float)(pix & 127u), y = (float)(pix >> 7);
            g_junc[2 * t + 0] = x + sigm(heat[7 * HW + pix]);
            g_junc[2 * t + 1] = y + sigm(heat[8 * HW + pix]);
        } else {
            g_junc[2 * t + 0] = 1e6f;
            g_junc[2 * t + 1] = 1e6f;
        }
    }
}

// ---------------- stage 3: HAFM decode + junction matching + id bitmap ----------------
__global__ void k_match(const float* __restrict__ heat) {
    __shared__ float sj[2 * KJ];
    for (int i = threadIdx.x; i < 2 * KJ; i += blockDim.x) sj[i] = g_junc[i];
    __syncthreads();
    int n = blockIdx.x * blockDim.x + threadIdx.x;
    if (n >= NLINES) return;
    int ch = n >> 14;
    int pix = n & (HW - 1);
    float x0 = (float)(pix & 127), y0 = (float)(pix >> 7);
    float a0   = sigm(heat[0 * HW + pix]);
    float a1   = sigm(heat[1 * HW + pix]);
    float a2   = sigm(heat[2 * HW + pix]);
    float dist = sigm(heat[3 * HW + pix]);
    float bias = sigm(heat[4 * HW + pix]);
    float d = dist + bias * (float)(ch - 1);
    d = fminf(fmaxf(d, 0.0f), 1.0f);
    float ang0 = (a0 - 0.5f) * PI_F * 2.0f;
    float c0 = cosf(ang0), s0 = sinf(ang0);
    float t1 =  tanf(a1 * (PI_F * 0.5f));
    float t2 = -tanf(a2 * (PI_F * 0.5f));
    float e1x = fminf(fmaxf((c0 - s0 * t1) * d * 5.0f + x0, 0.0f), 127.0f);
    float e1y = fminf(fmaxf((s0 + c0 * t1) * d * 5.0f + y0, 0.0f), 127.0f);
    float e2x = fminf(fmaxf((c0 - s0 * t2) * d * 5.0f + x0, 0.0f), 127.0f);
    float e2y = fminf(fmaxf((s0 + c0 * t2) * d * 5.0f + y0, 0.0f), 127.0f);

    int j1 = 0, j2 = 0;
    float m1 = 3.4e38f, m2 = 3.4e38f;
    #pragma unroll 4
    for (int k = 0; k < KJ; k++) {
        float jx = sj[2 * k], jy = sj[2 * k + 1];
        float dx = jx - e1x, dy = jy - e1y;
        float dd = dx * dx + dy * dy;
        if (dd < m1) { m1 = dd; j1 = k; }
        dx = jx - e2x; dy = jy - e2y;
        dd = dx * dx + dy * dy;
        if (dd < m2) { m2 = dd; j2 = k; }
    }
    int lo = min(j1, j2), hi = max(j1, j2);
    if (lo < hi) {
        int id = lo * KJ + hi;
        atomicOr(&g_bitmap[id >> 5], 1u << (id & 31));
    }
}

// ---------------- stage 4: ordered bitmap compaction (warp-scan) ----------------
__global__ void k_compact(float* __restrict__ dout) {
    __shared__ int wsum[32];
    int tid = threadIdx.x;
    int lane = tid & 31, wid = tid >> 5;
    int base = tid * 3;
    unsigned w[3] = {0u, 0u, 0u};
    int c = 0;
    #pragma unroll
    for (int q = 0; q < 3; q++) {
        int wi = base + q;
        if (wi < NBMW) { w[q] = g_bitmap[wi]; c += __popc(w[q]); }
    }
    int incl = c;
    #pragma unroll
    for (int o = 1; o < 32; o <<= 1) {
        int v = __shfl_up_sync(0xFFFFFFFFu, incl, o);
        if (lane >= o) incl += v;
    }
    if (lane == 31) wsum[wid] = incl;
    __syncthreads();
    if (wid == 0) {
        int s = wsum[lane];
        #pragma unroll
        for (int o = 1; o < 32; o <<= 1) {
            int v = __shfl_up_sync(0xFFFFFFFFu, s, o);
            if (lane >= o) s += v;
        }
        wsum[lane] = s;
    }
    __syncthreads();
    int pos = (wid ? wsum[wid - 1] : 0) + incl - c;   // exclusive prefix
    #pragma unroll
    for (int q = 0; q < 3; q++) {
        unsigned ww = w[q];
        int wbase = (base + q) * 32;
        while (ww) {
            int b = __ffs(ww) - 1;
            ww &= ww - 1;
            int id = wbase + b;
            int lo = id / KJ, hi = id - lo * KJ;
            dout[pos * 4 + 0] = g_junc[2 * lo + 0];
            dout[pos * 4 + 1] = g_junc[2 * lo + 1];
            dout[pos * 4 + 2] = g_junc[2 * hi + 0];
            dout[pos * 4 + 3] = g_junc[2 * hi + 1];
            pos++;
        }
    }
    if (tid == 1023) g_ctrs[1] = wsum[31];
}

// ---------------- stage 5: LOI GEMM via tf32 MMA (fused transpose of feat) ----------
// g_loi[p][o] = sum_c feat[c][p] * fc1w[o][c] + fc1b[o]
__global__ void __launch_bounds__(256, 2)
k_loi_mma(const float* __restrict__ feat, const float* __restrict__ fc1w,
          const float* __restrict__ fc1b) {
    __shared__ float As[128][33];   // [p][k]  (transposed feat, pad 33 conflict-free)
    __shared__ float Bs[128][33];   // [o][k]

    int tid  = threadIdx.x;
    int lane = tid & 31, wid = tid >> 5;
    int wm = (wid >> 2) * 64;       // warp p-base
    int wn = (wid & 3) * 32;        // warp o-base
    int g  = lane >> 2, tg = lane & 3;
    int p0 = blockIdx.x * 128;

    float c[4][4][4];
    #pragma unroll
    for (int mi = 0; mi < 4; mi++)
        #pragma unroll
        for (int ni = 0; ni < 4; ni++)
            #pragma unroll
            for (int r = 0; r < 4; r++) c[mi][ni][r] = 0.0f;

    for (int c0 = 0; c0 < 256; c0 += 32) {
        #pragma unroll
        for (int q = 0; q < 16; q++) {
            int f = tid + q * 256;
            int kc = f >> 7, p = f & 127;
            As[p][kc] = feat[(size_t)(c0 + kc) * HW + p0 + p];
        }
        #pragma unroll
        for (int q = 0; q < 16; q++) {
            int f = tid + q * 256;
            int cc = f & 31, o = f >> 5;
            Bs[o][cc] = fc1w[(size_t)o * 256 + c0 + cc];
        }
        __syncthreads();
        #pragma unroll
        for (int kk = 0; kk < 32; kk += 8) {
            unsigned a[4][4], b[4][2];
            #pragma unroll
            for (int mi = 0; mi < 4; mi++) {
                int r0 = wm + mi * 16 + g;
                a[mi][0] = __float_as_uint(As[r0][kk + tg]);
                a[mi][1] = __float_as_uint(As[r0 + 8][kk + tg]);
                a[mi][2] = __float_as_uint(As[r0][kk + tg + 4]);
                a[mi][3] = __float_as_uint(As[r0 + 8][kk + tg + 4]);
            }
            #pragma unroll
            for (int ni = 0; ni < 4; ni++) {
                int n0 = wn + ni * 8 + g;
                b[ni][0] = __float_as_uint(Bs[n0][kk + tg]);
                b[ni][1] = __float_as_uint(Bs[n0][kk + tg + 4]);
            }
            #pragma unroll
            for (int mi = 0; mi < 4; mi++)
                #pragma unroll
                for (int ni = 0; ni < 4; ni++)
                    asm volatile(
                        "mma.sync.aligned.m16n8k8.row.col.f32.tf32.tf32.f32 "
                        "{%0,%1,%2,%3}, {%4,%5,%6,%7}, {%8,%9}, {%0,%1,%2,%3};"
                        : "+f"(c[mi][ni][0]), "+f"(c[mi][ni][1]),
                          "+f"(c[mi][ni][2]), "+f"(c[mi][ni][3])
                        : "r"(a[mi][0]), "r"(a[mi][1]), "r"(a[mi][2]), "r"(a[mi][3]),
                          "r"(b[ni][0]), "r"(b[ni][1]));
        }
        __syncthreads();
    }

    #pragma unroll
    for (int mi = 0; mi < 4; mi++) {
        int p = p0 + wm + mi * 16 + g;
        #pragma unroll
        for (int ni = 0; ni < 4; ni++) {
            int o = wn + ni * 8 + 2 * tg;
            float bv0 = fc1b[o], bv1 = fc1b[o + 1];
            *(float2*)&g_loi[(size_t)p * 128 + o] =
                make_float2(c[mi][ni][0] + bv0, c[mi][ni][1] + bv1);
            *(float2*)&g_loi[(size_t)(p + 8) * 128 + o] =
                make_float2(c[mi][ni][2] + bv0, c[mi][ni][3] + bv1);
        }
    }
}

// ---------------- stage 6: bilinear sampling + maxpool4 -> feats[m][1024] ----------------
__global__ void k_sample(const float* __restrict__ dout) {
    int M = g_ctrs[1];
    int ch = threadIdx.x;      // 128 threads, one channel each
    for (int m = blockIdx.x; m < M; m += gridDim.x) {
        float x1 = dout[m * 4 + 0], y1 = dout[m * 4 + 1];
        float x2 = dout[m * 4 + 2], y2 = dout[m * 4 + 3];
        float mx = -3.4e38f;
        #pragma unroll 4
        for (int s = 0; s < 32; s++) {
            float t = (float)s / 31.0f;
            float px = x1 * t + x2 * (1.0f - t);
            float py = y1 * t + y2 * (1.0f - t);
            px = fminf(fmaxf(px, 0.0f), 127.0f);
            py = fminf(fmaxf(py, 0.0f), 127.0f);
            float fx0 = floorf(px), fy0 = floorf(py);
            int ix0 = (int)fx0, iy0 = (int)fy0;
            int ix1 = min(ix0 + 1, 127), iy1 = min(iy0 + 1, 127);
            float wx = px - fx0, wy = py - fy0;
            float v00 = g_loi[(size_t)(iy0 * 128 + ix0) * 128 + ch];
            float v01 = g_loi[(size_t)(iy0 * 128 + ix1) * 128 + ch];
            float v10 = g_loi[(size_t)(iy1 * 128 + ix0) * 128 + ch];
            float v11 = g_loi[(size_t)(iy1 * 128 + ix1) * 128 + ch];
            float v = v00 * (1.0f - wx) * (1.0f - wy) + v01 * wx * (1.0f - wy)
                    + v10 * (1.0f - wx) * wy + v11 * wx * wy;
            mx = ((s & 3) == 0) ? v : fmaxf(mx, v);
            if ((s & 3) == 3) g_bufA[(size_t)m * 1024 + ch * 8 + (s >> 2)] = mx;
        }
    }
}

// ---------------- stage 7: persistent MLP GEMM, tf32 mma, 2-stage cp.async ring ------
__global__ void __launch_bounds__(256, 2)
k_mlp_mma(const float* __restrict__ A, const float* __restrict__ Wm,
          const float* __restrict__ bias, float* __restrict__ Out) {
    __shared__ float As[2][128][20];   // pad 20: conflict-free frags, 16B rows
    __shared__ float Bs[2][128][20];

    int M = g_ctrs[1];
    int tiles = ((M + 127) >> 7) * 8;
    int tid  = threadIdx.x;
    int lane = tid & 31, wid = tid >> 5;
    int wm = (wid >> 2) * 64;
    int wn = (wid & 3) * 32;
    int g  = lane >> 2, tg = lane & 3;
    int r0g = tid >> 2, c4g = (tid & 3) * 4;   // global-load row/col (q=0); q=1 adds 64 rows

    for (int tile = blockIdx.x; tile < tiles; tile += gridDim.x) {
        int mt = tile >> 3, ot = tile & 7;
        const float* Aptr = A  + (size_t)(mt * 128) * 1024;
        const float* Bptr = Wm + (size_t)(ot * 128) * 1024;

        float c[4][4][4];
        #pragma unroll
        for (int mi = 0; mi < 4; mi++)
            #pragma unroll
            for (int ni = 0; ni < 4; ni++)
                #pragma unroll
                for (int r = 0; r < 4; r++) c[mi][ni][r] = 0.0f;

        // prologue: stage 0 (k0=0), stage 1 (k0=16)
        #pragma unroll
        for (int st = 0; st < 2; st++) {
            int k0 = st * 16;
            #pragma unroll
            for (int q = 0; q < 2; q++) {
                int row = r0g + q * 64;
                cp16(&As[st][row][c4g], &Aptr[(size_t)row * 1024 + k0 + c4g]);
                cp16(&Bs[st][row][c4g], &Bptr[(size_t)row * 1024 + k0 + c4g]);
            }
            cp_commit();
        }

        for (int kc = 0; kc < 64; kc++) {
            cp_wait1();
            __syncthreads();
            int st = kc & 1;
            #pragma unroll
            for (int kk = 0; kk < 16; kk += 8) {
                unsigned a[4][4], b[4][2];
                #pragma unroll
                for (int mi = 0; mi < 4; mi++) {
                    int r0 = wm + mi * 16 + g;
                    a[mi][0] = __float_as_uint(As[st][r0][kk + tg]);
                    a[mi][1] = __float_as_uint(As[st][r0 + 8][kk + tg]);
                    a[mi][2] = __float_as_uint(As[st][r0][kk + tg + 4]);
                    a[mi][3] = __float_as_uint(As[st][r0 + 8][kk + tg + 4]);
                }
                #pragma unroll
                for (int ni = 0; ni < 4; ni++) {
                    int n0 = wn + ni * 8 + g;
                    b[ni][0] = __float_as_uint(Bs[st][n0][kk + tg]);
                    b[ni][1] = __float_as_uint(Bs[st][n0][kk + tg + 4]);
                }
                #pragma unroll
                for (int mi = 0; mi < 4; mi++)
                    #pragma unroll
                    for (int ni = 0; ni < 4; ni++)
                        asm volatile(
                            "mma.sync.aligned.m16n8k8.row.col.f32.tf32.tf32.f32 "
                            "{%0,%1,%2,%3}, {%4,%5,%6,%7}, {%8,%9}, {%0,%1,%2,%3};"
                            : "+f"(c[mi][ni][0]), "+f"(c[mi][ni][1]),
                              "+f"(c[mi][ni][2]), "+f"(c[mi][ni][3])
                            : "r"(a[mi][0]), "r"(a[mi][1]), "r"(a[mi][2]), "r"(a[mi][3]),
                              "r"(b[ni][0]), "r"(b[ni][1]));
            }
            __syncthreads();
            if (kc < 62) {
                int k0 = (kc + 2) * 16;
                #pragma unroll
                for (int q = 0; q < 2; q++) {
                    int row = r0g + q * 64;
                    cp16(&As[st][row][c4g], &Aptr[(size_t)row * 1024 + k0 + c4g]);
                    cp16(&Bs[st][row][c4g], &Bptr[(size_t)row * 1024 + k0 + c4g]);
                }
                cp_commit();
            }
        }

        // epilogue: bias + relu
        #pragma unroll
        for (int mi = 0; mi < 4; mi++) {
            int m0 = mt * 128 + wm + mi * 16 + g;
            #pragma unroll
            for (int ni = 0; ni < 4; ni++) {
                int o = ot * 128 + wn + ni * 8 + 2 * tg;
                float bv0 = bias[o], bv1 = bias[o + 1];
                if (m0 < M) {
                    float2 v = make_float2(fmaxf(c[mi][ni][0] + bv0, 0.0f),
                                           fmaxf(c[mi][ni][1] + bv1, 0.0f));
                    *(float2*)&Out[(size_t)m0 * 1024 + o] = v;
                }
                if (m0 + 8 < M) {
                    float2 v = make_float2(fmaxf(c[mi][ni][2] + bv0, 0.0f),
                                           fmaxf(c[mi][ni][3] + bv1, 0.0f));
                    *(float2*)&Out[(size_t)(m0 + 8) * 1024 + o] = v;
                }
            }
        }
    }
}

// ---------------- stage 8: final dot + sigmoid ----------------
__global__ void k_final(const float* __restrict__ h2, const float* __restrict__ w3,
                        const float* __restrict__ b3, float* __restrict__ dout) {
    int M = g_ctrs[1];
    int gtid = blockIdx.x * blockDim.x + threadIdx.x;
    int warp = gtid >> 5;
    int lane = threadIdx.x & 31;
    int nwarps = (gridDim.x * blockDim.x) >> 5;
    for (int m = warp; m < M; m += nwarps) {
        float acc = 0.0f;
        #pragma unroll 8
        for (int c = lane; c < 1024; c += 32)
            acc += h2[(size_t)m * 1024 + c] * w3[c];
        #pragma unroll
        for (int o = 16; o > 0; o >>= 1) acc += __shfl_xor_sync(0xFFFFFFFFu, acc, o);
        if (lane == 0)
            dout[4 * NLINES + m] = 1.0f / (1.0f + expf(-(acc + b3[0])));
    }
}

// ---------------- launch ----------------
extern "C" void kernel_launch(void* const* d_in, const int* in_sizes, int n_in,
                              void* d_out, int out_size) {
    const float* features = (const float*)d_in[0];
    const float* heatmaps = (const float*)d_in[1];
    const float* fc1_w    = (const float*)d_in[2];
    const float* fc1_b    = (const float*)d_in[3];
    const float* w1       = (const float*)d_in[4];
    const float* b1       = (const float*)d_in[5];
    const float* w2       = (const float*)d_in[6];
    const float* b2       = (const float*)d_in[7];
    const float* w3       = (const float*)d_in[8];
    const float* b3       = (const float*)d_in[9];
    float* dout = (float*)d_out;

    // one-time side stream + events (created before capture; reused every call)
    static cudaStream_t s2 = nullptr;
    static cudaEvent_t evFork = nullptr, evJoin = nullptr;
    if (!s2) {
        cudaStreamCreateWithFlags(&s2, cudaStreamNonBlocking);
        cudaEventCreateWithFlags(&evFork, cudaEventDisableTiming);
        cudaEventCreateWithFlags(&evJoin, cudaEventDisableTiming);
    }

    void *p_ctrs, *p_bitmap;
    cudaGetSymbolAddress(&p_ctrs,   g_ctrs);
    cudaGetSymbolAddress(&p_bitmap, g_bitmap);
    (void)in_sizes; (void)n_in;

    cudaMemsetAsync(p_ctrs,   0, sizeof(int) * 2);
    cudaMemsetAsync(p_bitmap, 0, sizeof(unsigned int) * NBMW);
    cudaMemsetAsync(dout,     0, (size_t)out_size * sizeof(float));

    // fork: LOI GEMM on side stream, overlapping the latency-bound front-end chain
    cudaEventRecord(evFork, 0);
    cudaStreamWaitEvent(s2, evFork, 0);
    k_loi_mma<<<128, 256, 0, s2>>>(features, fc1_w, fc1_b);
    cudaEventRecord(evJoin, s2);

    k_prop<<<64, 256>>>(heatmaps);
    k_topk_sel<<<1, 1024>>>(heatmaps);
    k_match<<<192, 256>>>(heatmaps);
    k_compact<<<1, 1024>>>(dout);

    // join before sampling (needs both g_loi and line coords)
    cudaStreamWaitEvent(0, evJoin, 0);
    k_sample<<<512, 128>>>(dout);

    float* A = nullptr; float* B = nullptr;
    cudaGetSymbolAddress((void**)&A, g_bufA);
    cudaGetSymbolAddress((void**)&B, g_bufB);

    k_mlp_mma<<<296, 256>>>(A, w1, b1, B);
    k_mlp_mma<<<296, 256>>>(B, w2, b2, A);
    k_final<<<256, 128>>>(A, w3, b3, dout);
}

// round 9
// speedup vs baseline: 3.2481x; 1.2883x over previous
#include <cuda_runtime.h>
#include <cuda_fp16.h>
#include <math.h>

#define HW      16384
#define KJ      300
#define NLINES  49152
#define NBMW    2816            // 2816*32 = 90112 >= 90000 bits
#define MPAD    44928           // ceil(44850/128)*128
#define PI_F    3.14159265358979323846f

// ---------------- scratch (static device memory; no allocations) ----------------
__device__ unsigned long long  g_cand[4096];
__device__ int                 g_ctrs[2];     // [0]=cand count, [1]=line count
__device__ float               g_junc[2 * KJ];
__device__ unsigned int        g_bitmap[NBMW];
__device__ __align__(128) __half g_loi[(size_t)HW * 128];      // [pixel][channel] fp16
__device__ __align__(128) __half g_bufA[(size_t)MPAD * 1024];  // feats -> h2 (fp16)
__device__ __align__(128) __half g_bufB[(size_t)MPAD * 1024];  // h1 (fp16)
__device__ __align__(128) __half g_w1h[1024 * 1024];
__device__ __align__(128) __half g_w2h[1024 * 1024];

__device__ __forceinline__ float sigm(float x) { return 1.0f / (1.0f + expf(-x)); }

__device__ __forceinline__ void cp16(void* smem, const void* gptr) {
    unsigned s = (unsigned)__cvta_generic_to_shared(smem);
    asm volatile("cp.async.cg.shared.global [%0], [%1], 16;" :: "r"(s), "l"(gptr));
}
__device__ __forceinline__ void cp_commit() { asm volatile("cp.async.commit_group;"); }
__device__ __forceinline__ void cp_wait1()  { asm volatile("cp.async.wait_group 1;"); }

// ---------------- stage 0 (side stream): fp16 weight conversion ----------------
__global__ void k_cvt(const float* __restrict__ w1, const float* __restrict__ w2) {
    int i = blockIdx.x * blockDim.x + threadIdx.x;   // 0 .. 1M-1
    g_w1h[i] = __float2half(w1[i]);
    g_w2h[i] = __float2half(w2[i]);
}

// ---------------- stage 1 (fused): jloc + 3x3 NMS + candidate gather ----------------
__device__ __forceinline__ float jl(const float* __restrict__ heat, int p) {
    return 1.0f / (1.0f + expf(heat[5 * HW + p] - heat[6 * HW + p]));
}
__global__ void k_prop(const float* __restrict__ heat) {
    int i = blockIdx.x * blockDim.x + threadIdx.x;
    if (i >= HW) return;
    int y = i >> 7, x = i & 127;
    float v = jl(heat, i);
    float m = v;
    for (int dy = -1; dy <= 1; dy++) {
        int yy = y + dy; if ((unsigned)yy >= 128u) continue;
        for (int dx = -1; dx <= 1; dx++) {
            if (dy == 0 && dx == 0) continue;
            int xx = x + dx; if ((unsigned)xx >= 128u) continue;
            m = fmaxf(m, jl(heat, yy * 128 + xx));
        }
    }
    if (v == m && v > 0.0f) {
        int p = atomicAdd(&g_ctrs[0], 1);
        if (p < 4096) {
            unsigned long long key =
                ((unsigned long long)__float_as_uint(v) << 32) |
                (unsigned long long)(0xFFFFFFFFu - (unsigned)i);   // ties: lower idx first
            g_cand[p] = key;
        }
    }
}

// ---------------- stage 2: histogram select + small bitonic sort + junction coords ----
__global__ void k_topk_sel(const float* __restrict__ heat) {
    __shared__ unsigned long long sbuf[4096];   // aliased as 8192-bin u32 histogram
    __shared__ int sc[1024];
    __shared__ int sB, sTot, sPos;
    unsigned int* hist = (unsigned int*)sbuf;
    int t = threadIdx.x;
    int cc = g_ctrs[0];
    if (cc > 4096) cc = 4096;

    #pragma unroll
    for (int q = 0; q < 8; q++) hist[q * 1024 + t] = 0u;
    if (t == 0) { sPos = 0; sB = 0; sTot = 0; }
    __syncthreads();

    unsigned long long kk[4];
    #pragma unroll
    for (int q = 0; q < 4; q++) {
        int idx = q * 1024 + t;
        unsigned long long key = (idx < cc) ? g_cand[idx] : 0ULL;
        kk[q] = key;
        if (key >> 32)
            atomicAdd(&hist[(int)((key >> 50) & 0x1FFF)], 1u);
    }
    __syncthreads();

    int gs = 0;
    #pragma unroll
    for (int b = 0; b < 8; b++) gs += hist[t * 8 + b];
    sc[t] = gs;
    __syncthreads();
    for (int off = 1; off < 1024; off <<= 1) {
        int v = (t + off < 1024) ? sc[t + off] : 0;
        __syncthreads();
        sc[t] += v;
        __syncthreads();
    }
    int sufN = (t < 1023) ? sc[t + 1] : 0;
    if (t == 0 && sc[0] < KJ) { sB = 0; sTot = sc[0]; }
    if (sc[0] >= KJ && sc[t] >= KJ && sufN < KJ) {
        int run = sufN;
        for (int b = t * 8 + 7; b >= t * 8; b--) {
            run += hist[b];
            if (run >= KJ) { sB = b; sTot = run; break; }
        }
    }
    __syncthreads();
    int B = sB, total = sTot;

    #pragma unroll
    for (int q = 0; q < 4; q++) {
        unsigned long long key = kk[q];
        if ((key >> 32) && (int)((key >> 50) & 0x1FFF) >= B) {
            int p = atomicAdd(&sPos, 1);
            sbuf[p] = key;
        }
    }
    __syncthreads();

    int n = (total <= 512) ? 512 : (total <= 1024) ? 1024 : (total <= 2048) ? 2048 : 4096;
    for (int i = total + t; i < n; i += 1024) sbuf[i] = 0ULL;
    __syncthreads();

    for (int k = 2; k <= n; k <<= 1) {
        for (int j = k >> 1; j > 0; j >>= 1) {
            for (int i = t; i < n; i += 1024) {
                int ixj = i ^ j;
                if (ixj > i) {
                    unsigned long long a = sbuf[i], b = sbuf[ixj];
                    bool descSeg = (i & k) == 0;
                    if (descSeg ? (a < b) : (a > b)) { sbuf[i] = b; sbuf[ixj] = a; }
                }
            }
            __syncthreads();
        }
    }

    if (t < KJ) {
        unsigned long long key = sbuf[t];
        float v = __uint_as_float((unsigned)(key >> 32));
        if (v > 0.008f) {
            unsigned pix = 0xFFFFFFFFu - (unsigned)(key & 0xFFFFFFFFu);
            float x = (float)(pix & 127u), y = (float)(pix >> 7);
            g_junc[2 * t + 0] = x + sigm(heat[7 * HW + pix]);
            g_junc[2 * t + 1] = y + sigm(heat[8 * HW + pix]);
        } else {
            g_junc[2 * t + 0] = 1e6f;
            g_junc[2 * t + 1] = 1e6f;
        }
    }
}

// ---------------- stage 3: HAFM decode + matching (1 endpoint/thread) ----------------
__global__ void k_match(const float* __restrict__ heat) {
    __shared__ float sj[2 * KJ];
    for (int i = threadIdx.x; i < 2 * KJ; i += blockDim.x) sj[i] = g_junc[i];
    __syncthreads();
    int gtid = blockIdx.x * blockDim.x + threadIdx.x;
    if (gtid >= 2 * NLINES) return;
    int n = gtid >> 1;
    int e = gtid & 1;
    int ch = n >> 14;
    int pix = n & (HW - 1);
    float x0 = (float)(pix & 127), y0 = (float)(pix >> 7);
    float a0   = sigm(heat[0 * HW + pix]);
    float dist = sigm(heat[3 * HW + pix]);
    float bias = sigm(heat[4 * HW + pix]);
    float d = dist + bias * (float)(ch - 1);
    d = fminf(fmaxf(d, 0.0f), 1.0f);
    float ang0 = (a0 - 0.5f) * PI_F * 2.0f;
    float c0 = cosf(ang0), s0 = sinf(ang0);
    float te;
    if (e == 0) te =  tanf(sigm(heat[1 * HW + pix]) * (PI_F * 0.5f));
    else        te = -tanf(sigm(heat[2 * HW + pix]) * (PI_F * 0.5f));
    float ex = fminf(fmaxf((c0 - s0 * te) * d * 5.0f + x0, 0.0f), 127.0f);
    float ey = fminf(fmaxf((s0 + c0 * te) * d * 5.0f + y0, 0.0f), 127.0f);

    int j = 0;
    float mbest = 3.4e38f;
    const float2* sj2 = (const float2*)sj;
    #pragma unroll 4
    for (int k = 0; k < KJ; k++) {
        float2 jxy = sj2[k];
        float dx = jxy.x - ex, dy = jxy.y - ey;
        float dd = dx * dx + dy * dy;
        if (dd < mbest) { mbest = dd; j = k; }
    }
    int jo = __shfl_xor_sync(0xFFFFFFFFu, j, 1);
    if (e == 0) {
        int lo = min(j, jo), hi = max(j, jo);
        if (lo < hi) {
            int id = lo * KJ + hi;
            atomicOr(&g_bitmap[id >> 5], 1u << (id & 31));
        }
    }
}

// ---------------- stage 4: ordered bitmap compaction (warp-scan) ----------------
__global__ void k_compact(float* __restrict__ dout) {
    __shared__ int wsum[32];
    int tid = threadIdx.x;
    int lane = tid & 31, wid = tid >> 5;
    int base = tid * 3;
    unsigned w[3] = {0u, 0u, 0u};
    int c = 0;
    #pragma unroll
    for (int q = 0; q < 3; q++) {
        int wi = base + q;
        if (wi < NBMW) { w[q] = g_bitmap[wi]; c += __popc(w[q]); }
    }
    int incl = c;
    #pragma unroll
    for (int o = 1; o < 32; o <<= 1) {
        int v = __shfl_up_sync(0xFFFFFFFFu, incl, o);
        if (lane >= o) incl += v;
    }
    if (lane == 31) wsum[wid] = incl;
    __syncthreads();
    if (wid == 0) {
        int s = wsum[lane];
        #pragma unroll
        for (int o = 1; o < 32; o <<= 1) {
            int v = __shfl_up_sync(0xFFFFFFFFu, s, o);
            if (lane >= o) s += v;
        }
        wsum[lane] = s;
    }
    __syncthreads();
    int pos = (wid ? wsum[wid - 1] : 0) + incl - c;   // exclusive prefix
    #pragma unroll
    for (int q = 0; q < 3; q++) {
        unsigned ww = w[q];
        int wbase = (base + q) * 32;
        while (ww) {
            int b = __ffs(ww) - 1;
            ww &= ww - 1;
            int id = wbase + b;
            int lo = id / KJ, hi = id - lo * KJ;
            dout[pos * 4 + 0] = g_junc[2 * lo + 0];
            dout[pos * 4 + 1] = g_junc[2 * lo + 1];
            dout[pos * 4 + 2] = g_junc[2 * hi + 0];
            dout[pos * 4 + 3] = g_junc[2 * hi + 1];
            pos++;
        }
    }
    if (tid == 1023) g_ctrs[1] = wsum[31];
}

// ---------------- stage 5: LOI GEMM via tf32 MMA -> fp16 output ----------
// g_loi[p][o] = sum_c feat[c][p] * fc1w[o][c] + fc1b[o]
__global__ void __launch_bounds__(256, 2)
k_loi_mma(const float* __restrict__ feat, const float* __restrict__ fc1w,
          const float* __restrict__ fc1b) {
    __shared__ float As[128][33];   // [p][k]  (transposed feat)
    __shared__ float Bs[128][33];   // [o][k]

    int tid  = threadIdx.x;
    int lane = tid & 31, wid = tid >> 5;
    int wm = (wid >> 2) * 64;
    int wn = (wid & 3) * 32;
    int g  = lane >> 2, tg = lane & 3;
    int p0 = blockIdx.x * 128;

    float c[4][4][4];
    #pragma unroll
    for (int mi = 0; mi < 4; mi++)
        #pragma unroll
        for (int ni = 0; ni < 4; ni++)
            #pragma unroll
            for (int r = 0; r < 4; r++) c[mi][ni][r] = 0.0f;

    for (int c0 = 0; c0 < 256; c0 += 32) {
        #pragma unroll
        for (int q = 0; q < 16; q++) {
            int f = tid + q * 256;
            int kc = f >> 7, p = f & 127;
            As[p][kc] = feat[(size_t)(c0 + kc) * HW + p0 + p];
        }
        #pragma unroll
        for (int q = 0; q < 16; q++) {
            int f = tid + q * 256;
            int cc = f & 31, o = f >> 5;
            Bs[o][cc] = fc1w[(size_t)o * 256 + c0 + cc];
        }
        __syncthreads();
        #pragma unroll
        for (int kk = 0; kk < 32; kk += 8) {
            unsigned a[4][4], b[4][2];
            #pragma unroll
            for (int mi = 0; mi < 4; mi++) {
                int r0 = wm + mi * 16 + g;
                a[mi][0] = __float_as_uint(As[r0][kk + tg]);
                a[mi][1] = __float_as_uint(As[r0 + 8][kk + tg]);
                a[mi][2] = __float_as_uint(As[r0][kk + tg + 4]);
                a[mi][3] = __float_as_uint(As[r0 + 8][kk + tg + 4]);
            }
            #pragma unroll
            for (int ni = 0; ni < 4; ni++) {
                int n0 = wn + ni * 8 + g;
                b[ni][0] = __float_as_uint(Bs[n0][kk + tg]);
                b[ni][1] = __float_as_uint(Bs[n0][kk + tg + 4]);
            }
            #pragma unroll
            for (int mi = 0; mi < 4; mi++)
                #pragma unroll
                for (int ni = 0; ni < 4; ni++)
                    asm volatile(
                        "mma.sync.aligned.m16n8k8.row.col.f32.tf32.tf32.f32 "
                        "{%0,%1,%2,%3}, {%4,%5,%6,%7}, {%8,%9}, {%0,%1,%2,%3};"
                        : "+f"(c[mi][ni][0]), "+f"(c[mi][ni][1]),
                          "+f"(c[mi][ni][2]), "+f"(c[mi][ni][3])
                        : "r"(a[mi][0]), "r"(a[mi][1]), "r"(a[mi][2]), "r"(a[mi][3]),
                          "r"(b[ni][0]), "r"(b[ni][1]));
        }
        __syncthreads();
    }

    #pragma unroll
    for (int mi = 0; mi < 4; mi++) {
        int p = p0 + wm + mi * 16 + g;
        #pragma unroll
        for (int ni = 0; ni < 4; ni++) {
            int o = wn + ni * 8 + 2 * tg;
            float bv0 = fc1b[o], bv1 = fc1b[o + 1];
            *(__half2*)&g_loi[(size_t)p * 128 + o] =
                __floats2half2_rn(c[mi][ni][0] + bv0, c[mi][ni][1] + bv1);
            *(__half2*)&g_loi[(size_t)(p + 8) * 128 + o] =
                __floats2half2_rn(c[mi][ni][2] + bv0, c[mi][ni][3] + bv1);
        }
    }
}

// ---------------- stage 6: bilinear sampling + maxpool4 -> feats[m][1024] fp16 --------
__global__ void k_sample(const float* __restrict__ dout) {
    int M = g_ctrs[1];
    int ch = threadIdx.x;      // 128 threads, one channel each
    for (int m = blockIdx.x; m < M; m += gridDim.x) {
        float x1 = dout[m * 4 + 0], y1 = dout[m * 4 + 1];
        float x2 = dout[m * 4 + 2], y2 = dout[m * 4 + 3];
        float mx = -3.4e38f;
        #pragma unroll 4
        for (int s = 0; s < 32; s++) {
            float t = (float)s / 31.0f;
            float px = x1 * t + x2 * (1.0f - t);
            float py = y1 * t + y2 * (1.0f - t);
            px = fminf(fmaxf(px, 0.0f), 127.0f);
            py = fminf(fmaxf(py, 0.0f), 127.0f);
            float fx0 = floorf(px), fy0 = floorf(py);
            int ix0 = (int)fx0, iy0 = (int)fy0;
            int ix1 = min(ix0 + 1, 127), iy1 = min(iy0 + 1, 127);
            float wx = px - fx0, wy = py - fy0;
            float v00 = __half2float(g_loi[(size_t)(iy0 * 128 + ix0) * 128 + ch]);
            float v01 = __half2float(g_loi[(size_t)(iy0 * 128 + ix1) * 128 + ch]);
            float v10 = __half2float(g_loi[(size_t)(iy1 * 128 + ix0) * 128 + ch]);
            float v11 = __half2float(g_loi[(size_t)(iy1 * 128 + ix1) * 128 + ch]);
            float v = v00 * (1.0f - wx) * (1.0f - wy) + v01 * wx * (1.0f - wy)
                    + v10 * (1.0f - wx) * wy + v11 * wx * wy;
            mx = ((s & 3) == 0) ? v : fmaxf(mx, v);
            if ((s & 3) == 3) g_bufA[(size_t)m * 1024 + ch * 8 + (s >> 2)] = __float2half(mx);
        }
    }
}

// ---------------- stage 7: persistent MLP GEMM, fp16 m16n8k16, 2-stage cp.async ------
__global__ void __launch_bounds__(256, 2)
k_mlp_mma(const __half* __restrict__ A, const __half* __restrict__ Wm,
          const float* __restrict__ bias, __half* __restrict__ Out) {
    __shared__ __align__(16) __half As[2][128][40];   // 80B row stride: conflict-free
    __shared__ __align__(16) __half Bs[2][128][40];

    int M = g_ctrs[1];
    int tiles = ((M + 127) >> 7) * 8;
    int tid  = threadIdx.x;
    int lane = tid & 31, wid = tid >> 5;
    int wm = (wid >> 2) * 64;
    int wn = (wid & 3) * 32;
    int g  = lane >> 2, tg = lane & 3;

    for (int tile = blockIdx.x; tile < tiles; tile += gridDim.x) {
        int mt = tile >> 3, ot = tile & 7;
        const __half* Aptr = A  + (size_t)(mt * 128) * 1024;
        const __half* Bptr = Wm + (size_t)(ot * 128) * 1024;

        float c[4][4][4];
        #pragma unroll
        for (int mi = 0; mi < 4; mi++)
            #pragma unroll
            for (int ni = 0; ni < 4; ni++)
                #pragma unroll
                for (int r = 0; r < 4; r++) c[mi][ni][r] = 0.0f;

        // prologue: stages 0 (k0=0) and 1 (k0=32)
        #pragma unroll
        for (int st = 0; st < 2; st++) {
            int k0 = st * 32;
            #pragma unroll
            for (int q = 0; q < 2; q++) {
                int f = tid + q * 256;
                int row = f >> 2, ce = (f & 3) * 8;
                cp16(&As[st][row][ce], &Aptr[(size_t)row * 1024 + k0 + ce]);
                cp16(&Bs[st][row][ce], &Bptr[(size_t)row * 1024 + k0 + ce]);
            }
            cp_commit();
        }

        for (int kc = 0; kc < 32; kc++) {
            cp_wait1();
            __syncthreads();
            int st = kc & 1;
            #pragma unroll
            for (int kk = 0; kk < 32; kk += 16) {
                unsigned a[4][4], b[4][2];
                #pragma unroll
                for (int mi = 0; mi < 4; mi++) {
                    int r0 = wm + mi * 16 + g;
                    a[mi][0] = *(const unsigned*)&As[st][r0][kk + 2 * tg];
                    a[mi][1] = *(const unsigned*)&As[st][r0 + 8][kk + 2 * tg];
                    a[mi][2] = *(const unsigned*)&As[st][r0][kk + 2 * tg + 8];
                    a[mi][3] = *(const unsigned*)&As[st][r0 + 8][kk + 2 * tg + 8];
                }
                #pragma unroll
                for (int ni = 0; ni < 4; ni++) {
                    int n0 = wn + ni * 8 + g;
                    b[ni][0] = *(const unsigned*)&Bs[st][n0][kk + 2 * tg];
                    b[ni][1] = *(const unsigned*)&Bs[st][n0][kk + 2 * tg + 8];
                }
                #pragma unroll
                for (int mi = 0; mi < 4; mi++)
                    #pragma unroll
                    for (int ni = 0; ni < 4; ni++)
                        asm volatile(
                            "mma.sync.aligned.m16n8k16.row.col.f32.f16.f16.f32 "
                            "{%0,%1,%2,%3}, {%4,%5,%6,%7}, {%8,%9}, {%0,%1,%2,%3};"
                            : "+f"(c[mi][ni][0]), "+f"(c[mi][ni][1]),
                              "+f"(c[mi][ni][2]), "+f"(c[mi][ni][3])
                            : "r"(a[mi][0]), "r"(a[mi][1]), "r"(a[mi][2]), "r"(a[mi][3]),
                              "r"(b[ni][0]), "r"(b[ni][1]));
            }
            __syncthreads();
            if (kc < 30) {
                int k0 = (kc + 2) * 32;
                #pragma unroll
                for (int q = 0; q < 2; q++) {
                    int f = tid + q * 256;
                    int row = f >> 2, ce = (f & 3) * 8;
                    cp16(&As[st][row][ce], &Aptr[(size_t)row * 1024 + k0 + ce]);
                    cp16(&Bs[st][row][ce], &Bptr[(size_t)row * 1024 + k0 + ce]);
                }
                cp_commit();
            }
        }

        // epilogue: bias + relu -> fp16
        #pragma unroll
        for (int mi = 0; mi < 4; mi++) {
            int m0 = mt * 128 + wm + mi * 16 + g;
            #pragma unroll
            for (int ni = 0; ni < 4; ni++) {
                int o = ot * 128 + wn + ni * 8 + 2 * tg;
                float bv0 = bias[o], bv1 = bias[o + 1];
                if (m0 < M) {
                    *(__half2*)&Out[(size_t)m0 * 1024 + o] =
                        __floats2half2_rn(fmaxf(c[mi][ni][0] + bv0, 0.0f),
                                          fmaxf(c[mi][ni][1] + bv1, 0.0f));
                }
                if (m0 + 8 < M) {
                    *(__half2*)&Out[(size_t)(m0 + 8) * 1024 + o] =
                        __floats2half2_rn(fmaxf(c[mi][ni][2] + bv0, 0.0f),
                                          fmaxf(c[mi][ni][3] + bv1, 0.0f));
                }
            }
        }
    }
}

// ---------------- stage 8: final dot + sigmoid ----------------
__global__ void k_final(const __half* __restrict__ h2, const float* __restrict__ w3,
                        const float* __restrict__ b3, float* __restrict__ dout) {
    int M = g_ctrs[1];
    int gtid = blockIdx.x * blockDim.x + threadIdx.x;
    int warp = gtid >> 5;
    int lane = threadIdx.x & 31;
    int nwarps = (gridDim.x * blockDim.x) >> 5;
    for (int m = warp; m < M; m += nwarps) {
        float acc = 0.0f;
        #pragma unroll 8
        for (int c = lane; c < 1024; c += 32)
            acc += __half2float(h2[(size_t)m * 1024 + c]) * w3[c];
        #pragma unroll
        for (int o = 16; o > 0; o >>= 1) acc += __shfl_xor_sync(0xFFFFFFFFu, acc, o);
        if (lane == 0)
            dout[4 * NLINES + m] = 1.0f / (1.0f + expf(-(acc + b3[0])));
    }
}

// ---------------- launch ----------------
extern "C" void kernel_launch(void* const* d_in, const int* in_sizes, int n_in,
                              void* d_out, int out_size) {
    const float* features = (const float*)d_in[0];
    const float* heatmaps = (const float*)d_in[1];
    const float* fc1_w    = (const float*)d_in[2];
    const float* fc1_b    = (const float*)d_in[3];
    const float* w1       = (const float*)d_in[4];
    const float* b1       = (const float*)d_in[5];
    const float* w2       = (const float*)d_in[6];
    const float* b2       = (const float*)d_in[7];
    const float* w3       = (const float*)d_in[8];
    const float* b3       = (const float*)d_in[9];
    float* dout = (float*)d_out;

    static cudaStream_t s2 = nullptr;
    static cudaEvent_t evFork = nullptr, evJoin = nullptr;
    if (!s2) {
        cudaStreamCreateWithFlags(&s2, cudaStreamNonBlocking);
        cudaEventCreateWithFlags(&evFork, cudaEventDisableTiming);
        cudaEventCreateWithFlags(&evJoin, cudaEventDisableTiming);
    }

    void *p_ctrs, *p_bitmap;
    cudaGetSymbolAddress(&p_ctrs,   g_ctrs);
    cudaGetSymbolAddress(&p_bitmap, g_bitmap);
    (void)in_sizes; (void)n_in;

    cudaMemsetAsync(p_ctrs,   0, sizeof(int) * 2);
    cudaMemsetAsync(p_bitmap, 0, sizeof(unsigned int) * NBMW);
    cudaMemsetAsync(dout,     0, (size_t)out_size * sizeof(float));

    // fork: weight cvt + LOI GEMM on side stream, overlapping the front-end chain
    cudaEventRecord(evFork, 0);
    cudaStreamWaitEvent(s2, evFork, 0);
    k_cvt<<<4096, 256, 0, s2>>>(w1, w2);
    k_loi_mma<<<128, 256, 0, s2>>>(features, fc1_w, fc1_b);
    cudaEventRecord(evJoin, s2);

    k_prop<<<64, 256>>>(heatmaps);
    k_topk_sel<<<1, 1024>>>(heatmaps);
    k_match<<<384, 256>>>(heatmaps);
    k_compact<<<1, 1024>>>(dout);

    cudaStreamWaitEvent(0, evJoin, 0);
    k_sample<<<512, 128>>>(dout);

    __half* A = nullptr; __half* B = nullptr; __half* W1 = nullptr; __half* W2 = nullptr;
    cudaGetSymbolAddress((void**)&A,  g_bufA);
    cudaGetSymbolAddress((void**)&B,  g_bufB);
    cudaGetSymbolAddress((void**)&W1, g_w1h);
    cudaGetSymbolAddress((void**)&W2, g_w2h);

    k_mlp_mma<<<296, 256>>>(A, W1, b1, B);
    k_mlp_mma<<<296, 256>>>(B, W2, b2, A);
    k_final<<<256, 128>>>(A, w3, b3, dout);
}